// round 8
// baseline (speedup 1.0000x reference)
#include <cuda_runtime.h>
#include <cuda_bf16.h>
#include <math.h>
#include <stdint.h>

#define HID    768
#define INTER  3072
#define NHEAD  12
#define DH     64
#define NTOK   16384
#define WWIN   256
#define K1     (3 * HID)     // 2304  (tripled K for GEMM1)
#define KC2    (HID + INTER) // 3840  combined cols
#define K2     (3 * KC2)     // 11520 (tripled K for GEMM2)
#define QKVC   (3 * HID)     // 2304 fp32 qkv cols

// ---------------- scratch (device globals; allocation-free rule) ----------------
__device__ __align__(256) float          g_xn  [(size_t)NTOK * HID];
__device__ __align__(256) float          g_qkv [(size_t)NTOK * QKVC];
__device__ __align__(256) __nv_bfloat16  g_am1 [(size_t)NTOK * K1];
__device__ __align__(256) __nv_bfloat16  g_am2 [(size_t)NTOK * K2];
__device__ __align__(256) __nv_bfloat16  g_bm1 [(size_t)(3*HID+INTER) * K1];
__device__ __align__(256) __nv_bfloat16  g_bm2 [(size_t)HID * K2];

// ---------------- helpers ----------------
__device__ __forceinline__ uint32_t smem_u32(const void* p) {
    uint32_t a;
    asm("{ .reg .u64 t; cvta.to.shared.u64 t, %1; cvt.u32.u64 %0, t; }" : "=r"(a) : "l"(p));
    return a;
}
#define CPASYNC16(sa, gp) \
    asm volatile("cp.async.cg.shared.global [%0], [%1], 16;" :: "r"(sa), "l"(gp))
#define CP_COMMIT() asm volatile("cp.async.commit_group;" ::: "memory")
#define CP_WAIT1()  asm volatile("cp.async.wait_group 1;" ::: "memory")
#define CP_WAIT0()  asm volatile("cp.async.wait_group 0;" ::: "memory")
#define LDSM4(r0, r1, r2, r3, ad) \
    asm volatile("ldmatrix.sync.aligned.m8n8.x4.shared.b16 {%0,%1,%2,%3}, [%4];" \
                 : "=r"(r0), "=r"(r1), "=r"(r2), "=r"(r3) : "r"(ad))
#define MMA16816(d, a, b0, b1) \
    asm volatile("mma.sync.aligned.m16n8k16.row.col.f32.bf16.bf16.f32 " \
                 "{%0,%1,%2,%3}, {%4,%5,%6,%7}, {%8,%9}, {%0,%1,%2,%3};" \
                 : "+f"((d)[0]), "+f"((d)[1]), "+f"((d)[2]), "+f"((d)[3]) \
                 : "r"((a)[0]), "r"((a)[1]), "r"((a)[2]), "r"((a)[3]), "r"(b0), "r"(b1))

__device__ __forceinline__ void bf16_split(float v, __nv_bfloat16& hi, __nv_bfloat16& lo) {
    hi = __float2bfloat16(v);
    lo = __float2bfloat16(v - __bfloat162float(hi));
}

// ---------------- LayerNorm + A-triple emit for GEMM1 ----------------
__global__ void ln_kernel(const float* __restrict__ x,
                          const float* __restrict__ gamma,
                          const float* __restrict__ beta) {
    const int row = blockIdx.x, t = threadIdx.x;
    const float* xr = x + (size_t)row * HID;
    float v0 = xr[t], v1 = xr[t + 256], v2 = xr[t + 512];
    float s  = v0 + v1 + v2;
    float ss = v0 * v0 + v1 * v1 + v2 * v2;
    #pragma unroll
    for (int o = 16; o; o >>= 1) {
        s  += __shfl_xor_sync(0xffffffffu, s,  o);
        ss += __shfl_xor_sync(0xffffffffu, ss, o);
    }
    __shared__ float sh[18];
    if ((t & 31) == 0) { sh[t >> 5] = s; sh[(t >> 5) + 8] = ss; }
    __syncthreads();
    if (t == 0) {
        float S = 0.f, SS = 0.f;
        #pragma unroll
        for (int i = 0; i < 8; i++) { S += sh[i]; SS += sh[i + 8]; }
        float mu  = S * (1.0f / HID);
        float var = SS * (1.0f / HID) - mu * mu;
        sh[16] = mu;
        sh[17] = rsqrtf(var + 1e-5f);
    }
    __syncthreads();
    const float mu = sh[16], rs = sh[17];
    float* o = g_xn + (size_t)row * HID;
    __nv_bfloat16* a1 = g_am1 + (size_t)row * K1;
    #pragma unroll
    for (int g = 0; g < 3; g++) {
        const int c = t + g * 256;
        const float v = (g == 0 ? v0 : (g == 1 ? v1 : v2));
        const float y = (v - mu) * rs * gamma[c] + beta[c];
        o[c] = y;
        __nv_bfloat16 hi, lo; bf16_split(y, hi, lo);
        a1[3 * c]     = hi;   // A triple [hi, hi, lo]
        a1[3 * c + 1] = hi;
        a1[3 * c + 2] = lo;
    }
}

// ---------------- weight transpose + B-triple [hi, lo, hi] ----------------
__global__ void conv_w_kernel(const float* __restrict__ w, __nv_bfloat16* __restrict__ bm,
                              int Kdim, int Ndim) {
    __shared__ float tile[32][33];
    const int k0 = blockIdx.y << 5, n0 = blockIdx.x << 5;
    const int tx = threadIdx.x & 31, tr = threadIdx.x >> 5;
    #pragma unroll
    for (int r = 0; r < 32; r += 8)
        tile[tr + r][tx] = w[(size_t)(k0 + tr + r) * Ndim + n0 + tx];
    __syncthreads();
    const int nl = threadIdx.x & 31;
    const int kq = threadIdx.x >> 5;   // 4 k's per thread
    __align__(8) __nv_bfloat16 t[12];
    #pragma unroll
    for (int j = 0; j < 4; j++) {
        float v = tile[kq * 4 + j][nl];
        __nv_bfloat16 hi, lo; bf16_split(v, hi, lo);
        t[3*j] = hi; t[3*j+1] = lo; t[3*j+2] = hi;
    }
    unsigned long long* dp = (unsigned long long*)
        (bm + (size_t)(n0 + nl) * (3 * (size_t)Kdim) + 3 * (size_t)(k0 + kq * 4));
    const unsigned long long* ts = (const unsigned long long*)t;
    dp[0] = ts[0]; dp[1] = ts[1]; dp[2] = ts[2];
}

// ---------------- mma.sync GEMM: C[M,N] = A[M,K] * B[N,K]^T ----------------
// CTA 128M x 256N, BK=64, 512 threads (4x4 warps, warp 32x64), 3-stage cp.async.
__global__ __launch_bounds__(512, 1)
void gemm_mma(const __nv_bfloat16* __restrict__ A, const __nv_bfloat16* __restrict__ B,
              const float* __restrict__ bias, const float* __restrict__ resid,
              float* __restrict__ outF, float* __restrict__ outQKV,
              __nv_bfloat16* __restrict__ outT, int K, int mode)
{
    extern __shared__ char sm[];
    const uint32_t sb = smem_u32(sm);
    const int tid = threadIdx.x, lane = tid & 31, wid = tid >> 5;
    const int m0 = blockIdx.y << 7, n0 = blockIdx.x << 8;
    const int wm = wid & 3, wn = wid >> 2;

    auto load_stage = [&](int c, int s) {
        const int kc = c << 6;
        const __nv_bfloat16* Ab = A + (size_t)m0 * K + kc;
        const __nv_bfloat16* Bb = B + (size_t)n0 * K + kc;
        const uint32_t stA = sb + s * 49152;
        const uint32_t stB = stA + 16384;
        #pragma unroll
        for (int i = 0; i < 2; i++) {         // A: 128 rows
            const int cid = tid + (i << 9);
            const int row = cid >> 3, ch = cid & 7;
            const uint32_t so = row * 128 + ((ch ^ (row & 7)) << 4);
            CPASYNC16(stA + so, Ab + (size_t)row * K + (ch << 3));
        }
        #pragma unroll
        for (int i = 0; i < 4; i++) {         // B: 256 rows
            const int cid = tid + (i << 9);
            const int row = cid >> 3, ch = cid & 7;
            const uint32_t so = row * 128 + ((ch ^ (row & 7)) << 4);
            CPASYNC16(stB + so, Bb + (size_t)row * K + (ch << 3));
        }
    };

    // ldmatrix lane bases
    const int la = lane & 7;
    const int rowA0 = wm * 32 + la + ((lane >> 3) & 1) * 8;   // + mf*16
    const int swA   = rowA0 & 7;
    const int cbA   = (lane >> 4) & 1;
    const int rowB0 = wn * 64 + la + ((lane >> 4) & 1) * 8;   // + nf2*16
    const int swB   = rowB0 & 7;
    const int cbB   = (lane >> 3) & 1;

    float acc[2][8][4];
    #pragma unroll
    for (int i = 0; i < 2; i++)
        #pragma unroll
        for (int j = 0; j < 8; j++)
            #pragma unroll
            for (int q = 0; q < 4; q++) acc[i][j][q] = 0.f;

    const int nc = K >> 6;
    load_stage(0, 0); CP_COMMIT();
    load_stage(1, 1); CP_COMMIT();

    for (int c = 0; c < nc; c++) {
        CP_WAIT1();
        __syncthreads();
        if (c + 2 < nc) load_stage(c + 2, (c + 2) % 3);
        CP_COMMIT();

        const uint32_t stA = sb + (c % 3) * 49152;
        const uint32_t stB = stA + 16384;
        #pragma unroll
        for (int kk = 0; kk < 4; kk++) {
            uint32_t a[2][4];
            #pragma unroll
            for (int mf = 0; mf < 2; mf++) {
                const uint32_t ad = stA + (rowA0 + mf * 16) * 128 + (((kk * 2 + cbA) ^ swA) << 4);
                LDSM4(a[mf][0], a[mf][1], a[mf][2], a[mf][3], ad);
            }
            uint32_t b[4][4];
            #pragma unroll
            for (int nf2 = 0; nf2 < 4; nf2++) {
                const uint32_t bd = stB + (rowB0 + nf2 * 16) * 128 + (((kk * 2 + cbB) ^ swB) << 4);
                LDSM4(b[nf2][0], b[nf2][1], b[nf2][2], b[nf2][3], bd);
            }
            #pragma unroll
            for (int mf = 0; mf < 2; mf++)
                #pragma unroll
                for (int nf = 0; nf < 8; nf++)
                    MMA16816(acc[mf][nf], a[mf], b[nf >> 1][(nf & 1) * 2], b[nf >> 1][(nf & 1) * 2 + 1]);
        }
        __syncthreads();
    }
    CP_WAIT0();
    __syncthreads();

    // stage C (128 x 256) into smem, rows padded to 260 floats
    float* smC = (float*)sm;
    #pragma unroll
    for (int mf = 0; mf < 2; mf++)
        #pragma unroll
        for (int nf = 0; nf < 8; nf++)
            #pragma unroll
            for (int q = 0; q < 4; q++) {
                const int row = wm * 32 + mf * 16 + (lane >> 2) + ((q >> 1) << 3);
                const int col = wn * 64 + nf * 8 + ((lane & 3) << 1) + (q & 1);
                smC[row * 260 + col] = acc[mf][nf][q];
            }
    __syncthreads();

    // epilogue: row = tid/4, 64-col quarter = tid&3
    const int r  = tid >> 2, hf = tid & 3;
    const int mrow = m0 + r;
    const int nb   = n0 + hf * 64;
    const float* cr = smC + r * 260 + hf * 64;

    if (mode == 1) {
        if (nb < 3 * HID) {
            float* dst = outQKV + (size_t)mrow * QKVC + nb;
            #pragma unroll
            for (int q = 0; q < 16; q++) {
                float4 ov;
                ov.x = cr[q*4+0] + bias[nb+q*4+0];
                ov.y = cr[q*4+1] + bias[nb+q*4+1];
                ov.z = cr[q*4+2] + bias[nb+q*4+2];
                ov.w = cr[q*4+3] + bias[nb+q*4+3];
                *(float4*)(dst + q * 4) = ov;
            }
        } else {
            __align__(16) __nv_bfloat16 trip[192];
            #pragma unroll
            for (int i = 0; i < 64; i++) {
                float v = cr[i] + bias[nb + i];
                float u = v * (0.7978845608028654f + 0.0356774081f * v * v);
                v = 0.5f * v * (1.0f + tanhf(u));
                __nv_bfloat16 hi, lo; bf16_split(v, hi, lo);
                trip[3*i] = hi; trip[3*i+1] = hi; trip[3*i+2] = lo;
            }
            uint4* dp = (uint4*)(outT + (size_t)mrow * K2 + (3 * nb - 6 * HID));
            const uint4* ts = (const uint4*)trip;
            #pragma unroll
            for (int j = 0; j < 24; j++) dp[j] = ts[j];
        }
    } else {
        float* dst = outF + (size_t)mrow * HID + nb;
        const float* rp = resid + (size_t)mrow * HID + nb;
        #pragma unroll
        for (int q = 0; q < 16; q++) {
            float4 rv = *(const float4*)(rp + q * 4);
            float4 ov;
            ov.x = cr[q*4+0] + bias[nb+q*4+0] + rv.x;
            ov.y = cr[q*4+1] + bias[nb+q*4+1] + rv.y;
            ov.z = cr[q*4+2] + bias[nb+q*4+2] + rv.z;
            ov.w = cr[q*4+3] + bias[nb+q*4+3] + rv.w;
            *(float4*)(dst + q * 4) = ov;
        }
    }
}

// ---------------- RoPE (in-place on g_qkv q,k cols) ----------------
__global__ void rope_kernel(const float* __restrict__ psin, const float* __restrict__ pcos) {
    const int idx = blockIdx.x * blockDim.x + threadIdx.x;
    if (idx >= NTOK * 768) return;
    const int row = idx / 768;
    const int p   = idx - row * 768;
    const int col = p << 1;
    const int d   = col & (DH - 1);
    float2* ptr = (float2*)(g_qkv + (size_t)row * QKVC + col);
    const float2 eo = *ptr;
    const float c = pcos[row * DH + d];
    const float s = psin[row * DH + d];
    float2 r;
    r.x = eo.x * c - eo.y * s;
    r.y = eo.y * c + eo.x * s;
    *ptr = r;
}

// ---------------- Sliding-window attention ----------------
// block = (128-query chunk, head); THREAD PAIR per query (each owns 32 dims).
__global__ __launch_bounds__(256, 2)
void attn_kernel(const int* __restrict__ plen) {
    __shared__ float Ks[64][DH];
    __shared__ float Vs[64][DH];
    const int h    = blockIdx.y;
    const int q0   = blockIdx.x << 7;          // 128 queries per block
    const int tid  = threadIdx.x;
    const int ql   = tid >> 1;                 // local query 0..127
    const int half = tid & 1;                  // dim half
    const int qi   = q0 + ql;
    const int dof  = half << 5;                // 0 or 32
    const unsigned lm   = ~((unsigned)(*plen) - 1u);
    const unsigned qseg = (unsigned)qi & lm;

    float q[32], acc[32];
    {
        const float* qp = g_qkv + (size_t)qi * QKVC + h * DH + dof;
        #pragma unroll
        for (int i = 0; i < 8; i++) *(float4*)&q[i * 4] = *(const float4*)(qp + i * 4);
    }
    #pragma unroll
    for (int i = 0; i < 32; i++) acc[i] = 0.f;
    float m = -1e30f, l = 0.f;

    const int r   = tid >> 2;
    const int sg  = (tid & 3) << 4;
    const int wid = tid >> 5;
    const int qw0 = q0 + wid * 16;             // warp's first query

    for (int t = 0; t < 6; t++) {
        const int kbase = q0 - 256 + t * 64;
        __syncthreads();
        {   // load 64-key K/V tile
            const int kj = kbase + r;
            float4* dK = (float4*)&Ks[r][sg];
            float4* dV = (float4*)&Vs[r][sg];
            if (kj >= 0) {
                const float* kp = g_qkv + (size_t)kj * QKVC + HID + h * DH + sg;
                const float* vp = kp + HID;
                #pragma unroll
                for (int i = 0; i < 4; i++) dK[i] = ((const float4*)kp)[i];
                #pragma unroll
                for (int i = 0; i < 4; i++) dV[i] = ((const float4*)vp)[i];
            } else {
                const float4 z = make_float4(0.f, 0.f, 0.f, 0.f);
                #pragma unroll
                for (int i = 0; i < 4; i++) { dK[i] = z; dV[i] = z; }
            }
        }
        __syncthreads();
        int jlo = qw0 - 255 - kbase; if (jlo < 0) jlo = 0;   // warp-uniform
        int jhi = qw0 + 15  - kbase; if (jhi > 63) jhi = 63;
        for (int j = jlo; j <= jhi; j++) {
            // partial dot over this thread's 32 dims, combined with pair via shfl
            float sh_ = 0.f;
            #pragma unroll
            for (int d4 = 0; d4 < 8; d4++) {
                const float4 kv = *(const float4*)&Ks[j][dof + d4 * 4];
                sh_ += q[d4*4+0]*kv.x + q[d4*4+1]*kv.y + q[d4*4+2]*kv.z + q[d4*4+3]*kv.w;
            }
            float s = sh_ + __shfl_xor_sync(0xffffffffu, sh_, 1);
            const int kj  = kbase + j;
            const int dlt = qi - kj;
            const bool valid = (kj >= 0) & (dlt >= 0) & (dlt < WWIN) &
                               (((unsigned)kj & lm) == qseg);
            s = valid ? s * 0.125f : -3e30f;   // invalid -> p underflows to 0
            if (s > m) {
                const float sf = __expf(m - s);
                l *= sf;
                #pragma unroll
                for (int d = 0; d < 32; d++) acc[d] *= sf;
                m = s;
            }
            const float p = __expf(s - m);
            l += p;
            #pragma unroll
            for (int d4 = 0; d4 < 8; d4++) {
                const float4 vv = *(const float4*)&Vs[j][dof + d4 * 4];
                acc[d4*4+0] = fmaf(p, vv.x, acc[d4*4+0]);
                acc[d4*4+1] = fmaf(p, vv.y, acc[d4*4+1]);
                acc[d4*4+2] = fmaf(p, vv.z, acc[d4*4+2]);
                acc[d4*4+3] = fmaf(p, vv.w, acc[d4*4+3]);
            }
        }
    }
    const float inv = 1.f / l;
    __nv_bfloat16* op = g_am2 + (size_t)qi * K2 + 192 * h + half * 96;
    #pragma unroll
    for (int g = 0; g < 8; g++) {
        __align__(16) __nv_bfloat16 tbuf[12];
        #pragma unroll
        for (int j = 0; j < 4; j++) {
            float v = acc[g * 4 + j] * inv;
            __nv_bfloat16 hi, lo; bf16_split(v, hi, lo);
            tbuf[3*j] = hi; tbuf[3*j+1] = hi; tbuf[3*j+2] = lo;
        }
        unsigned long long* dp = (unsigned long long*)(op + 12 * g);
        const unsigned long long* ts = (const unsigned long long*)tbuf;
        dp[0] = ts[0]; dp[1] = ts[1]; dp[2] = ts[2];
    }
}

// ---------------- launch ----------------
extern "C" void kernel_launch(void* const* d_in, const int* in_sizes, int n_in,
                              void* d_out, int out_size) {
    const float* x        = (const float*)d_in[0];
    const float* psin     = (const float*)d_in[2];
    const float* pcos     = (const float*)d_in[3];
    const float* ln_scale = (const float*)d_in[4];
    const float* ln_off   = (const float*)d_in[5];
    const float* w_in     = (const float*)d_in[6];
    const float* b_in     = (const float*)d_in[7];
    const float* w_out    = (const float*)d_in[8];
    const float* b_out    = (const float*)d_in[9];
    const int*   plen     = (const int*)d_in[10];
    float* out = (float*)d_out;

    float *p_xn = nullptr, *p_qkv = nullptr;
    __nv_bfloat16 *p_am1 = nullptr, *p_am2 = nullptr, *p_bm1 = nullptr, *p_bm2 = nullptr;
    cudaGetSymbolAddress((void**)&p_xn,  g_xn);
    cudaGetSymbolAddress((void**)&p_qkv, g_qkv);
    cudaGetSymbolAddress((void**)&p_am1, g_am1);
    cudaGetSymbolAddress((void**)&p_am2, g_am2);
    cudaGetSymbolAddress((void**)&p_bm1, g_bm1);
    cudaGetSymbolAddress((void**)&p_bm2, g_bm2);

    static bool attr_set = false;
    const int gsmem = 3 * 49152;   // 144 KB: 3 stages; reused as 128x260 C stage
    if (!attr_set) {
        cudaFuncSetAttribute(gemm_mma, cudaFuncAttributeMaxDynamicSharedMemorySize, gsmem);
        attr_set = true;
    }

    conv_w_kernel<<<dim3((3*HID+INTER)/32, HID/32), 256>>>(w_in,  p_bm1, HID, 3*HID+INTER);
    conv_w_kernel<<<dim3(HID/32, KC2/32),           256>>>(w_out, p_bm2, KC2, HID);

    ln_kernel<<<NTOK, 256>>>(x, ln_scale, ln_off);

    // GEMM1: [NTOK x 5376]
    gemm_mma<<<dim3((3*HID+INTER)/256, NTOK/128), 512, gsmem>>>(
        p_am1, p_bm1, b_in, nullptr, nullptr, p_qkv, p_am2, K1, 1);

    rope_kernel<<<(NTOK * 768) / 256, 256>>>(psin, pcos);

    attn_kernel<<<dim3(NTOK/128, NHEAD), 256>>>(plen);

    // GEMM2: out = xn + am2 @ bm2^T + b_out
    gemm_mma<<<dim3(HID/256, NTOK/128), 512, gsmem>>>(
        p_am2, p_bm2, b_out, p_xn, out, nullptr, nullptr, K2, 2);
}

// round 9
// speedup vs baseline: 1.3593x; 1.3593x over previous
#include <cuda_runtime.h>
#include <cuda_fp16.h>
#include <math.h>
#include <stdint.h>

#define HID    768
#define INTER  3072
#define NHEAD  12
#define DH     64
#define NTOK   16384
#define WWIN   256
#define K1     (2 * HID)     // 1536  (doubled K for GEMM1, fp16 2-term)
#define KC2    (HID + INTER) // 3840  combined cols
#define K2     (2 * KC2)     // 7680  (doubled K for GEMM2)
#define QKVC   (3 * HID)     // 2304 fp32 qkv cols

// ---------------- scratch (device globals; allocation-free rule) ----------------
__device__ __align__(256) float   g_xn  [(size_t)NTOK * HID];
__device__ __align__(256) float   g_qkv [(size_t)NTOK * QKVC];
__device__ __align__(256) __half  g_am1 [(size_t)NTOK * K1];
__device__ __align__(256) __half  g_am2 [(size_t)NTOK * K2];
__device__ __align__(256) __half  g_bm1 [(size_t)(3*HID+INTER) * K1];
__device__ __align__(256) __half  g_bm2 [(size_t)HID * K2];

// ---------------- helpers ----------------
__device__ __forceinline__ uint32_t smem_u32(const void* p) {
    uint32_t a;
    asm("{ .reg .u64 t; cvta.to.shared.u64 t, %1; cvt.u32.u64 %0, t; }" : "=r"(a) : "l"(p));
    return a;
}
#define CPASYNC16(sa, gp) \
    asm volatile("cp.async.cg.shared.global [%0], [%1], 16;" :: "r"(sa), "l"(gp))
#define CP_COMMIT() asm volatile("cp.async.commit_group;" ::: "memory")
#define CP_WAIT1()  asm volatile("cp.async.wait_group 1;" ::: "memory")
#define CP_WAIT0()  asm volatile("cp.async.wait_group 0;" ::: "memory")
#define LDSM4(r0, r1, r2, r3, ad) \
    asm volatile("ldmatrix.sync.aligned.m8n8.x4.shared.b16 {%0,%1,%2,%3}, [%4];" \
                 : "=r"(r0), "=r"(r1), "=r"(r2), "=r"(r3) : "r"(ad))
#define MMA16816(d, a, b0, b1) \
    asm volatile("mma.sync.aligned.m16n8k16.row.col.f32.f16.f16.f32 " \
                 "{%0,%1,%2,%3}, {%4,%5,%6,%7}, {%8,%9}, {%0,%1,%2,%3};" \
                 : "+f"((d)[0]), "+f"((d)[1]), "+f"((d)[2]), "+f"((d)[3]) \
                 : "r"((a)[0]), "r"((a)[1]), "r"((a)[2]), "r"((a)[3]), "r"(b0), "r"(b1))

__device__ __forceinline__ void fp16_split(float v, __half& hi, __half& lo) {
    hi = __float2half_rn(v);
    lo = __float2half_rn(v - __half2float(hi));
}

// ---------------- LayerNorm + A-pair emit for GEMM1 ----------------
__global__ void ln_kernel(const float* __restrict__ x,
                          const float* __restrict__ gamma,
                          const float* __restrict__ beta) {
    const int row = blockIdx.x, t = threadIdx.x;
    const float* xr = x + (size_t)row * HID;
    float v0 = xr[t], v1 = xr[t + 256], v2 = xr[t + 512];
    float s  = v0 + v1 + v2;
    float ss = v0 * v0 + v1 * v1 + v2 * v2;
    #pragma unroll
    for (int o = 16; o; o >>= 1) {
        s  += __shfl_xor_sync(0xffffffffu, s,  o);
        ss += __shfl_xor_sync(0xffffffffu, ss, o);
    }
    __shared__ float sh[18];
    if ((t & 31) == 0) { sh[t >> 5] = s; sh[(t >> 5) + 8] = ss; }
    __syncthreads();
    if (t == 0) {
        float S = 0.f, SS = 0.f;
        #pragma unroll
        for (int i = 0; i < 8; i++) { S += sh[i]; SS += sh[i + 8]; }
        float mu  = S * (1.0f / HID);
        float var = SS * (1.0f / HID) - mu * mu;
        sh[16] = mu;
        sh[17] = rsqrtf(var + 1e-5f);
    }
    __syncthreads();
    const float mu = sh[16], rs = sh[17];
    float* o = g_xn + (size_t)row * HID;
    __half2* a1 = (__half2*)(g_am1 + (size_t)row * K1);
    #pragma unroll
    for (int g = 0; g < 3; g++) {
        const int c = t + g * 256;
        const float v = (g == 0 ? v0 : (g == 1 ? v1 : v2));
        const float y = (v - mu) * rs * gamma[c] + beta[c];
        o[c] = y;
        __half hi, lo; fp16_split(y, hi, lo);
        a1[c] = __halves2half2(hi, lo);    // A pair [hi, lo]
    }
}

// ---------------- weight transpose + B-pair [hi, hi] ----------------
// w[Kdim][Ndim] fp32 -> bm[Ndim][2*Kdim] fp16
__global__ void conv_w_kernel(const float* __restrict__ w, __half* __restrict__ bm,
                              int Kdim, int Ndim) {
    __shared__ float tile[32][33];
    const int k0 = blockIdx.y << 5, n0 = blockIdx.x << 5;
    const int tx = threadIdx.x & 31, tr = threadIdx.x >> 5;
    #pragma unroll
    for (int r = 0; r < 32; r += 8)
        tile[tr + r][tx] = w[(size_t)(k0 + tr + r) * Ndim + n0 + tx];
    __syncthreads();
    const int nl = threadIdx.x & 31;
    const int kq = threadIdx.x >> 5;   // 4 k's per thread
    __align__(16) __half t[8];
    #pragma unroll
    for (int j = 0; j < 4; j++) {
        float v = tile[kq * 4 + j][nl];
        __half hi = __float2half_rn(v);
        t[2*j] = hi; t[2*j+1] = hi;    // B pair [hi, hi]
    }
    uint4* dp = (uint4*)(bm + (size_t)(n0 + nl) * (2 * (size_t)Kdim) + 2 * (size_t)(k0 + kq * 4));
    *dp = *(const uint4*)t;
}

// ---------------- mma.sync GEMM: C[M,N] = A[M,K] * B[N,K]^T ----------------
// CTA 128x128, BK=64, 256 threads (4x2 warps, warp 32x64), 3-stage cp.async.
__global__ __launch_bounds__(256)
void gemm_mma(const __half* __restrict__ A, const __half* __restrict__ B,
              const float* __restrict__ bias, const float* __restrict__ resid,
              float* __restrict__ outF, float* __restrict__ outQKV,
              __half* __restrict__ outT, int K, int mode)
{
    extern __shared__ char sm[];
    const uint32_t sb = smem_u32(sm);
    const int tid = threadIdx.x, lane = tid & 31, wid = tid >> 5;
    const int m0 = blockIdx.y << 7, n0 = blockIdx.x << 7;
    const int wm = wid & 3, wn = wid >> 2;

    auto load_stage = [&](int c, int s) {
        const int kc = c << 6;
        const __half* Ab = A + (size_t)m0 * K + kc;
        const __half* Bb = B + (size_t)n0 * K + kc;
        const uint32_t stA = sb + s * 32768;
        const uint32_t stB = stA + 16384;
        #pragma unroll
        for (int i = 0; i < 4; i++) {
            const int cid = tid + (i << 8);
            const int row = cid >> 3, ch = cid & 7;
            const uint32_t so = row * 128 + ((ch ^ (row & 7)) << 4);
            CPASYNC16(stA + so, Ab + (size_t)row * K + (ch << 3));
            CPASYNC16(stB + so, Bb + (size_t)row * K + (ch << 3));
        }
    };

    // ldmatrix lane bases
    const int la = lane & 7;
    const int rowA0 = wm * 32 + la + ((lane >> 3) & 1) * 8;   // + mf*16
    const int swA   = rowA0 & 7;
    const int cbA   = (lane >> 4) & 1;
    const int rowB0 = wn * 64 + la + ((lane >> 4) & 1) * 8;   // + nf2*16
    const int swB   = rowB0 & 7;
    const int cbB   = (lane >> 3) & 1;

    float acc[2][8][4];
    #pragma unroll
    for (int i = 0; i < 2; i++)
        #pragma unroll
        for (int j = 0; j < 8; j++)
            #pragma unroll
            for (int q = 0; q < 4; q++) acc[i][j][q] = 0.f;

    const int nc = K >> 6;
    load_stage(0, 0); CP_COMMIT();
    load_stage(1, 1); CP_COMMIT();

    for (int c = 0; c < nc; c++) {
        CP_WAIT1();
        __syncthreads();
        if (c + 2 < nc) load_stage(c + 2, (c + 2) % 3);
        CP_COMMIT();

        const uint32_t stA = sb + (c % 3) * 32768;
        const uint32_t stB = stA + 16384;
        #pragma unroll
        for (int kk = 0; kk < 4; kk++) {
            uint32_t a[2][4];
            #pragma unroll
            for (int mf = 0; mf < 2; mf++) {
                const uint32_t ad = stA + (rowA0 + mf * 16) * 128 + (((kk * 2 + cbA) ^ swA) << 4);
                LDSM4(a[mf][0], a[mf][1], a[mf][2], a[mf][3], ad);
            }
            uint32_t b[4][4];
            #pragma unroll
            for (int nf2 = 0; nf2 < 4; nf2++) {
                const uint32_t bd = stB + (rowB0 + nf2 * 16) * 128 + (((kk * 2 + cbB) ^ swB) << 4);
                LDSM4(b[nf2][0], b[nf2][1], b[nf2][2], b[nf2][3], bd);
            }
            #pragma unroll
            for (int mf = 0; mf < 2; mf++)
                #pragma unroll
                for (int nf = 0; nf < 8; nf++)
                    MMA16816(acc[mf][nf], a[mf], b[nf >> 1][(nf & 1) * 2], b[nf >> 1][(nf & 1) * 2 + 1]);
        }
        __syncthreads();
    }
    CP_WAIT0();
    __syncthreads();

    // stage C tile into smem, rows padded to 132 floats
    float* smC = (float*)sm;
    #pragma unroll
    for (int mf = 0; mf < 2; mf++)
        #pragma unroll
        for (int nf = 0; nf < 8; nf++)
            #pragma unroll
            for (int q = 0; q < 4; q++) {
                const int row = wm * 32 + mf * 16 + (lane >> 2) + ((q >> 1) << 3);
                const int col = wn * 64 + nf * 8 + ((lane & 3) << 1) + (q & 1);
                smC[row * 132 + col] = acc[mf][nf][q];
            }
    __syncthreads();

    // per-thread epilogue: row = tid/2, 64-col half = tid&1
    const int r  = tid >> 1, hf = tid & 1;
    const int mrow = m0 + r;
    const int nb   = n0 + hf * 64;
    const float* cr = smC + r * 132 + hf * 64;

    if (mode == 1) {
        if (nb < 3 * HID) {
            float* dst = outQKV + (size_t)mrow * QKVC + nb;
            #pragma unroll
            for (int q = 0; q < 16; q++) {
                float4 ov;
                ov.x = cr[q*4+0] + bias[nb+q*4+0];
                ov.y = cr[q*4+1] + bias[nb+q*4+1];
                ov.z = cr[q*4+2] + bias[nb+q*4+2];
                ov.w = cr[q*4+3] + bias[nb+q*4+3];
                *(float4*)(dst + q * 4) = ov;
            }
        } else {
            __align__(16) __half pr[128];
            #pragma unroll
            for (int i = 0; i < 64; i++) {
                float v = cr[i] + bias[nb + i];
                float u = v * (0.7978845608028654f + 0.0356774081f * v * v);
                v = 0.5f * v * (1.0f + tanhf(u));
                __half hi, lo; fp16_split(v, hi, lo);
                pr[2*i] = hi; pr[2*i+1] = lo;
            }
            // combined col = HID + (nb - 3*HID) -> elem offset 2*nb - 4*HID
            uint4* dp = (uint4*)(outT + (size_t)mrow * K2 + (2 * nb - 4 * HID));
            const uint4* ts = (const uint4*)pr;
            #pragma unroll
            for (int j = 0; j < 16; j++) dp[j] = ts[j];
        }
    } else {
        float* dst = outF + (size_t)mrow * HID + nb;
        const float* rp = resid + (size_t)mrow * HID + nb;
        #pragma unroll
        for (int q = 0; q < 16; q++) {
            float4 rv = *(const float4*)(rp + q * 4);
            float4 ov;
            ov.x = cr[q*4+0] + bias[nb+q*4+0] + rv.x;
            ov.y = cr[q*4+1] + bias[nb+q*4+1] + rv.y;
            ov.z = cr[q*4+2] + bias[nb+q*4+2] + rv.z;
            ov.w = cr[q*4+3] + bias[nb+q*4+3] + rv.w;
            *(float4*)(dst + q * 4) = ov;
        }
    }
}

// ---------------- RoPE (in-place on g_qkv q,k cols) ----------------
__global__ void rope_kernel(const float* __restrict__ psin, const float* __restrict__ pcos) {
    const int idx = blockIdx.x * blockDim.x + threadIdx.x;
    if (idx >= NTOK * 768) return;
    const int row = idx / 768;
    const int p   = idx - row * 768;
    const int col = p << 1;
    const int d   = col & (DH - 1);
    float2* ptr = (float2*)(g_qkv + (size_t)row * QKVC + col);
    const float2 eo = *ptr;
    const float c = pcos[row * DH + d];
    const float s = psin[row * DH + d];
    float2 r;
    r.x = eo.x * c - eo.y * s;
    r.y = eo.y * c + eo.x * s;
    *ptr = r;
}

// ---------------- Sliding-window attention ----------------
// block = (128-query chunk, head); thread pair per query (each owns 32 dims).
__global__ __launch_bounds__(256, 2)
void attn_kernel(const int* __restrict__ plen) {
    __shared__ float Ks[64][DH];
    __shared__ float Vs[64][DH];
    const int h    = blockIdx.y;
    const int q0   = blockIdx.x << 7;          // 128 queries per block
    const int tid  = threadIdx.x;
    const int ql   = tid >> 1;
    const int half = tid & 1;
    const int qi   = q0 + ql;
    const int dof  = half << 5;
    const unsigned lm   = ~((unsigned)(*plen) - 1u);
    const unsigned qseg = (unsigned)qi & lm;

    float q[32], acc[32];
    {
        const float* qp = g_qkv + (size_t)qi * QKVC + h * DH + dof;
        #pragma unroll
        for (int i = 0; i < 8; i++) *(float4*)&q[i * 4] = *(const float4*)(qp + i * 4);
    }
    #pragma unroll
    for (int i = 0; i < 32; i++) acc[i] = 0.f;
    float m = -1e30f, l = 0.f;

    const int r   = tid >> 2;
    const int sg  = (tid & 3) << 4;
    const int wid = tid >> 5;
    const int qw0 = q0 + wid * 16;             // warp's first query

    for (int t = 0; t < 6; t++) {
        const int kbase = q0 - 256 + t * 64;
        __syncthreads();
        {   // load 64-key K/V tile
            const int kj = kbase + r;
            float4* dK = (float4*)&Ks[r][sg];
            float4* dV = (float4*)&Vs[r][sg];
            if (kj >= 0) {
                const float* kp = g_qkv + (size_t)kj * QKVC + HID + h * DH + sg;
                const float* vp = kp + HID;
                #pragma unroll
                for (int i = 0; i < 4; i++) dK[i] = ((const float4*)kp)[i];
                #pragma unroll
                for (int i = 0; i < 4; i++) dV[i] = ((const float4*)vp)[i];
            } else {
                const float4 z = make_float4(0.f, 0.f, 0.f, 0.f);
                #pragma unroll
                for (int i = 0; i < 4; i++) { dK[i] = z; dV[i] = z; }
            }
        }
        __syncthreads();
        int jlo = qw0 - 255 - kbase; if (jlo < 0) jlo = 0;   // warp-uniform
        int jhi = qw0 + 15  - kbase; if (jhi > 63) jhi = 63;
        for (int j = jlo; j <= jhi; j++) {
            float sh_ = 0.f;
            #pragma unroll
            for (int d4 = 0; d4 < 8; d4++) {
                const float4 kv = *(const float4*)&Ks[j][dof + d4 * 4];
                sh_ += q[d4*4+0]*kv.x + q[d4*4+1]*kv.y + q[d4*4+2]*kv.z + q[d4*4+3]*kv.w;
            }
            float s = sh_ + __shfl_xor_sync(0xffffffffu, sh_, 1);
            const int kj  = kbase + j;
            const int dlt = qi - kj;
            const bool valid = (kj >= 0) & (dlt >= 0) & (dlt < WWIN) &
                               (((unsigned)kj & lm) == qseg);
            s = valid ? s * 0.125f : -3e30f;   // invalid -> p underflows to 0
            if (s > m) {
                const float sf = __expf(m - s);
                l *= sf;
                #pragma unroll
                for (int d = 0; d < 32; d++) acc[d] *= sf;
                m = s;
            }
            const float p = __expf(s - m);
            l += p;
            #pragma unroll
            for (int d4 = 0; d4 < 8; d4++) {
                const float4 vv = *(const float4*)&Vs[j][dof + d4 * 4];
                acc[d4*4+0] = fmaf(p, vv.x, acc[d4*4+0]);
                acc[d4*4+1] = fmaf(p, vv.y, acc[d4*4+1]);
                acc[d4*4+2] = fmaf(p, vv.z, acc[d4*4+2]);
                acc[d4*4+3] = fmaf(p, vv.w, acc[d4*4+3]);
            }
        }
    }
    const float inv = 1.f / l;
    __half* op = g_am2 + (size_t)qi * K2 + 128 * h + half * 64;   // 2*(h*64 + dof)
    #pragma unroll
    for (int g = 0; g < 8; g++) {
        __align__(16) __half tbuf[8];
        #pragma unroll
        for (int j = 0; j < 4; j++) {
            float v = acc[g * 4 + j] * inv;
            __half hi, lo; fp16_split(v, hi, lo);
            tbuf[2*j] = hi; tbuf[2*j+1] = lo;
        }
        *(uint4*)(op + 8 * g) = *(const uint4*)tbuf;
    }
}

// ---------------- launch ----------------
extern "C" void kernel_launch(void* const* d_in, const int* in_sizes, int n_in,
                              void* d_out, int out_size) {
    const float* x        = (const float*)d_in[0];
    const float* psin     = (const float*)d_in[2];
    const float* pcos     = (const float*)d_in[3];
    const float* ln_scale = (const float*)d_in[4];
    const float* ln_off   = (const float*)d_in[5];
    const float* w_in     = (const float*)d_in[6];
    const float* b_in     = (const float*)d_in[7];
    const float* w_out    = (const float*)d_in[8];
    const float* b_out    = (const float*)d_in[9];
    const int*   plen     = (const int*)d_in[10];
    float* out = (float*)d_out;

    float *p_xn = nullptr, *p_qkv = nullptr;
    __half *p_am1 = nullptr, *p_am2 = nullptr, *p_bm1 = nullptr, *p_bm2 = nullptr;
    cudaGetSymbolAddress((void**)&p_xn,  g_xn);
    cudaGetSymbolAddress((void**)&p_qkv, g_qkv);
    cudaGetSymbolAddress((void**)&p_am1, g_am1);
    cudaGetSymbolAddress((void**)&p_am2, g_am2);
    cudaGetSymbolAddress((void**)&p_bm1, g_bm1);
    cudaGetSymbolAddress((void**)&p_bm2, g_bm2);

    static bool attr_set = false;
    const int gsmem = 3 * 32768;   // 96 KB: 3 stages; reused as 128x132 C stage
    if (!attr_set) {
        cudaFuncSetAttribute(gemm_mma, cudaFuncAttributeMaxDynamicSharedMemorySize, gsmem);
        attr_set = true;
    }

    conv_w_kernel<<<dim3((3*HID+INTER)/32, HID/32), 256>>>(w_in,  p_bm1, HID, 3*HID+INTER);
    conv_w_kernel<<<dim3(HID/32, KC2/32),           256>>>(w_out, p_bm2, KC2, HID);

    ln_kernel<<<NTOK, 256>>>(x, ln_scale, ln_off);

    // GEMM1: [NTOK x 5376]
    gemm_mma<<<dim3((3*HID+INTER)/128, NTOK/128), 256, gsmem>>>(
        p_am1, p_bm1, b_in, nullptr, nullptr, p_qkv, p_am2, K1, 1);

    rope_kernel<<<(NTOK * 768) / 256, 256>>>(psin, pcos);

    attn_kernel<<<dim3(NTOK/128, NHEAD), 256>>>(plen);

    // GEMM2: out = xn + am2 @ bm2^T + b_out
    gemm_mma<<<dim3(HID/128, NTOK/128), 256, gsmem>>>(
        p_am2, p_bm2, b_out, p_xn, out, nullptr, nullptr, K2, 2);
}

// round 10
// speedup vs baseline: 1.8030x; 1.3264x over previous
#include <cuda_runtime.h>
#include <cuda_fp16.h>
#include <math.h>
#include <stdint.h>

#define HID    768
#define INTER  3072
#define NHEAD  12
#define DH     64
#define NTOK   16384
#define WWIN   256
#define K1     HID           // 768   (plain fp16 GEMM1)
#define KC2    (HID + INTER) // 3840  combined cols
#define K2     KC2           // 3840  (plain fp16 GEMM2)
#define QKVC   (3 * HID)     // 2304 fp32 qkv cols

// ---------------- scratch (device globals; allocation-free rule) ----------------
__device__ __align__(256) float   g_xn  [(size_t)NTOK * HID];
__device__ __align__(256) float   g_qkv [(size_t)NTOK * QKVC];
__device__ __align__(256) __half  g_am1 [(size_t)NTOK * K1];
__device__ __align__(256) __half  g_am2 [(size_t)NTOK * K2];
__device__ __align__(256) __half  g_bm1 [(size_t)(3*HID+INTER) * K1];
__device__ __align__(256) __half  g_bm2 [(size_t)HID * K2];

// ---------------- helpers ----------------
__device__ __forceinline__ uint32_t smem_u32(const void* p) {
    uint32_t a;
    asm("{ .reg .u64 t; cvta.to.shared.u64 t, %1; cvt.u32.u64 %0, t; }" : "=r"(a) : "l"(p));
    return a;
}
#define CPASYNC16(sa, gp) \
    asm volatile("cp.async.cg.shared.global [%0], [%1], 16;" :: "r"(sa), "l"(gp))
#define CP_COMMIT() asm volatile("cp.async.commit_group;" ::: "memory")
#define CP_WAIT1()  asm volatile("cp.async.wait_group 1;" ::: "memory")
#define CP_WAIT0()  asm volatile("cp.async.wait_group 0;" ::: "memory")
#define LDSM4(r0, r1, r2, r3, ad) \
    asm volatile("ldmatrix.sync.aligned.m8n8.x4.shared.b16 {%0,%1,%2,%3}, [%4];" \
                 : "=r"(r0), "=r"(r1), "=r"(r2), "=r"(r3) : "r"(ad))
#define MMA16816(d, a, b0, b1) \
    asm volatile("mma.sync.aligned.m16n8k16.row.col.f32.f16.f16.f32 " \
                 "{%0,%1,%2,%3}, {%4,%5,%6,%7}, {%8,%9}, {%0,%1,%2,%3};" \
                 : "+f"((d)[0]), "+f"((d)[1]), "+f"((d)[2]), "+f"((d)[3]) \
                 : "r"((a)[0]), "r"((a)[1]), "r"((a)[2]), "r"((a)[3]), "r"(b0), "r"(b1))

// ---------------- LayerNorm + fp16 A emit for GEMM1 ----------------
__global__ void ln_kernel(const float* __restrict__ x,
                          const float* __restrict__ gamma,
                          const float* __restrict__ beta) {
    const int row = blockIdx.x, t = threadIdx.x;
    const float* xr = x + (size_t)row * HID;
    float v0 = xr[t], v1 = xr[t + 256], v2 = xr[t + 512];
    float s  = v0 + v1 + v2;
    float ss = v0 * v0 + v1 * v1 + v2 * v2;
    #pragma unroll
    for (int o = 16; o; o >>= 1) {
        s  += __shfl_xor_sync(0xffffffffu, s,  o);
        ss += __shfl_xor_sync(0xffffffffu, ss, o);
    }
    __shared__ float sh[18];
    if ((t & 31) == 0) { sh[t >> 5] = s; sh[(t >> 5) + 8] = ss; }
    __syncthreads();
    if (t == 0) {
        float S = 0.f, SS = 0.f;
        #pragma unroll
        for (int i = 0; i < 8; i++) { S += sh[i]; SS += sh[i + 8]; }
        float mu  = S * (1.0f / HID);
        float var = SS * (1.0f / HID) - mu * mu;
        sh[16] = mu;
        sh[17] = rsqrtf(var + 1e-5f);
    }
    __syncthreads();
    const float mu = sh[16], rs = sh[17];
    float* o = g_xn + (size_t)row * HID;
    __half* a1 = g_am1 + (size_t)row * K1;
    #pragma unroll
    for (int g = 0; g < 3; g++) {
        const int c = t + g * 256;
        const float v = (g == 0 ? v0 : (g == 1 ? v1 : v2));
        const float y = (v - mu) * rs * gamma[c] + beta[c];
        o[c] = y;
        a1[c] = __float2half_rn(y);
    }
}

// ---------------- weight transpose to fp16: w[Kdim][Ndim] -> bm[Ndim][Kdim] ----------------
__global__ void conv_w_kernel(const float* __restrict__ w, __half* __restrict__ bm,
                              int Kdim, int Ndim) {
    __shared__ float tile[32][33];
    const int k0 = blockIdx.y << 5, n0 = blockIdx.x << 5;
    const int tx = threadIdx.x & 31, tr = threadIdx.x >> 5;
    #pragma unroll
    for (int r = 0; r < 32; r += 8)
        tile[tr + r][tx] = w[(size_t)(k0 + tr + r) * Ndim + n0 + tx];
    __syncthreads();
    const int nl = threadIdx.x & 31;
    const int kq = threadIdx.x >> 5;   // 4 k's per thread
    __align__(8) __half t[4];
    #pragma unroll
    for (int j = 0; j < 4; j++)
        t[j] = __float2half_rn(tile[kq * 4 + j][nl]);
    uint2* dp = (uint2*)(bm + (size_t)(n0 + nl) * (size_t)Kdim + (size_t)(k0 + kq * 4));
    *dp = *(const uint2*)t;
}

// ---------------- mma.sync GEMM: C[M,N] = A[M,K] * B[N,K]^T ----------------
// CTA 128x128, BK=64, 256 threads (4x2 warps, warp 32x64), 3-stage cp.async.
__global__ __launch_bounds__(256)
void gemm_mma(const __half* __restrict__ A, const __half* __restrict__ B,
              const float* __restrict__ bias, const float* __restrict__ resid,
              float* __restrict__ outF, float* __restrict__ outQKV,
              __half* __restrict__ outT, int K, int mode)
{
    extern __shared__ char sm[];
    const uint32_t sb = smem_u32(sm);
    const int tid = threadIdx.x, lane = tid & 31, wid = tid >> 5;
    const int m0 = blockIdx.y << 7, n0 = blockIdx.x << 7;
    const int wm = wid & 3, wn = wid >> 2;

    auto load_stage = [&](int c, int s) {
        const int kc = c << 6;
        const __half* Ab = A + (size_t)m0 * K + kc;
        const __half* Bb = B + (size_t)n0 * K + kc;
        const uint32_t stA = sb + s * 32768;
        const uint32_t stB = stA + 16384;
        #pragma unroll
        for (int i = 0; i < 4; i++) {
            const int cid = tid + (i << 8);
            const int row = cid >> 3, ch = cid & 7;
            const uint32_t so = row * 128 + ((ch ^ (row & 7)) << 4);
            CPASYNC16(stA + so, Ab + (size_t)row * K + (ch << 3));
            CPASYNC16(stB + so, Bb + (size_t)row * K + (ch << 3));
        }
    };

    // ldmatrix lane bases
    const int la = lane & 7;
    const int rowA0 = wm * 32 + la + ((lane >> 3) & 1) * 8;   // + mf*16
    const int swA   = rowA0 & 7;
    const int cbA   = (lane >> 4) & 1;
    const int rowB0 = wn * 64 + la + ((lane >> 4) & 1) * 8;   // + nf2*16
    const int swB   = rowB0 & 7;
    const int cbB   = (lane >> 3) & 1;

    float acc[2][8][4];
    #pragma unroll
    for (int i = 0; i < 2; i++)
        #pragma unroll
        for (int j = 0; j < 8; j++)
            #pragma unroll
            for (int q = 0; q < 4; q++) acc[i][j][q] = 0.f;

    const int nc = K >> 6;
    load_stage(0, 0); CP_COMMIT();
    load_stage(1, 1); CP_COMMIT();

    for (int c = 0; c < nc; c++) {
        CP_WAIT1();
        __syncthreads();
        if (c + 2 < nc) load_stage(c + 2, (c + 2) % 3);
        CP_COMMIT();

        const uint32_t stA = sb + (c % 3) * 32768;
        const uint32_t stB = stA + 16384;
        #pragma unroll
        for (int kk = 0; kk < 4; kk++) {
            uint32_t a[2][4];
            #pragma unroll
            for (int mf = 0; mf < 2; mf++) {
                const uint32_t ad = stA + (rowA0 + mf * 16) * 128 + (((kk * 2 + cbA) ^ swA) << 4);
                LDSM4(a[mf][0], a[mf][1], a[mf][2], a[mf][3], ad);
            }
            uint32_t b[4][4];
            #pragma unroll
            for (int nf2 = 0; nf2 < 4; nf2++) {
                const uint32_t bd = stB + (rowB0 + nf2 * 16) * 128 + (((kk * 2 + cbB) ^ swB) << 4);
                LDSM4(b[nf2][0], b[nf2][1], b[nf2][2], b[nf2][3], bd);
            }
            #pragma unroll
            for (int mf = 0; mf < 2; mf++)
                #pragma unroll
                for (int nf = 0; nf < 8; nf++)
                    MMA16816(acc[mf][nf], a[mf], b[nf >> 1][(nf & 1) * 2], b[nf >> 1][(nf & 1) * 2 + 1]);
        }
        __syncthreads();
    }
    CP_WAIT0();
    __syncthreads();

    // stage C tile into smem, rows padded to 132 floats
    float* smC = (float*)sm;
    #pragma unroll
    for (int mf = 0; mf < 2; mf++)
        #pragma unroll
        for (int nf = 0; nf < 8; nf++)
            #pragma unroll
            for (int q = 0; q < 4; q++) {
                const int row = wm * 32 + mf * 16 + (lane >> 2) + ((q >> 1) << 3);
                const int col = wn * 64 + nf * 8 + ((lane & 3) << 1) + (q & 1);
                smC[row * 132 + col] = acc[mf][nf][q];
            }
    __syncthreads();

    // per-thread epilogue: row = tid/2, 64-col half = tid&1
    const int r  = tid >> 1, hf = tid & 1;
    const int mrow = m0 + r;
    const int nb   = n0 + hf * 64;
    const float* cr = smC + r * 132 + hf * 64;

    if (mode == 1) {
        if (nb < 3 * HID) {
            float* dst = outQKV + (size_t)mrow * QKVC + nb;
            #pragma unroll
            for (int q = 0; q < 16; q++) {
                float4 ov;
                ov.x = cr[q*4+0] + bias[nb+q*4+0];
                ov.y = cr[q*4+1] + bias[nb+q*4+1];
                ov.z = cr[q*4+2] + bias[nb+q*4+2];
                ov.w = cr[q*4+3] + bias[nb+q*4+3];
                *(float4*)(dst + q * 4) = ov;
            }
        } else {
            __align__(16) __half pr[64];
            #pragma unroll
            for (int i = 0; i < 64; i++) {
                float v = cr[i] + bias[nb + i];
                float u = v * (0.7978845608028654f + 0.0356774081f * v * v);
                v = 0.5f * v * (1.0f + tanhf(u));
                pr[i] = __float2half_rn(v);
            }
            // combined col = HID + (nb - 3*HID) = nb - 2*HID
            uint4* dp = (uint4*)(outT + (size_t)mrow * K2 + (nb - 2 * HID));
            const uint4* ts = (const uint4*)pr;
            #pragma unroll
            for (int j = 0; j < 8; j++) dp[j] = ts[j];
        }
    } else {
        float* dst = outF + (size_t)mrow * HID + nb;
        const float* rp = resid + (size_t)mrow * HID + nb;
        #pragma unroll
        for (int q = 0; q < 16; q++) {
            float4 rv = *(const float4*)(rp + q * 4);
            float4 ov;
            ov.x = cr[q*4+0] + bias[nb+q*4+0] + rv.x;
            ov.y = cr[q*4+1] + bias[nb+q*4+1] + rv.y;
            ov.z = cr[q*4+2] + bias[nb+q*4+2] + rv.z;
            ov.w = cr[q*4+3] + bias[nb+q*4+3] + rv.w;
            *(float4*)(dst + q * 4) = ov;
        }
    }
}

// ---------------- RoPE (in-place on g_qkv q,k cols) ----------------
__global__ void rope_kernel(const float* __restrict__ psin, const float* __restrict__ pcos) {
    const int idx = blockIdx.x * blockDim.x + threadIdx.x;
    if (idx >= NTOK * 768) return;
    const int row = idx / 768;
    const int p   = idx - row * 768;
    const int col = p << 1;
    const int d   = col & (DH - 1);
    float2* ptr = (float2*)(g_qkv + (size_t)row * QKVC + col);
    const float2 eo = *ptr;
    const float c = pcos[row * DH + d];
    const float s = psin[row * DH + d];
    float2 r;
    r.x = eo.x * c - eo.y * s;
    r.y = eo.y * c + eo.x * s;
    *ptr = r;
}

// ---------------- Sliding-window attention ----------------
// block = (128-query chunk, head); thread pair per query (each owns 32 dims).
__global__ __launch_bounds__(256, 2)
void attn_kernel(const int* __restrict__ plen) {
    __shared__ float Ks[64][DH];
    __shared__ float Vs[64][DH];
    const int h    = blockIdx.y;
    const int q0   = blockIdx.x << 7;          // 128 queries per block
    const int tid  = threadIdx.x;
    const int ql   = tid >> 1;
    const int half = tid & 1;
    const int qi   = q0 + ql;
    const int dof  = half << 5;
    const unsigned lm   = ~((unsigned)(*plen) - 1u);
    const unsigned qseg = (unsigned)qi & lm;

    float q[32], acc[32];
    {
        const float* qp = g_qkv + (size_t)qi * QKVC + h * DH + dof;
        #pragma unroll
        for (int i = 0; i < 8; i++) *(float4*)&q[i * 4] = *(const float4*)(qp + i * 4);
    }
    #pragma unroll
    for (int i = 0; i < 32; i++) acc[i] = 0.f;
    float m = -1e30f, l = 0.f;

    const int r   = tid >> 2;
    const int sg  = (tid & 3) << 4;
    const int wid = tid >> 5;
    const int qw0 = q0 + wid * 16;             // warp's first query

    for (int t = 0; t < 6; t++) {
        const int kbase = q0 - 256 + t * 64;
        __syncthreads();
        {   // load 64-key K/V tile
            const int kj = kbase + r;
            float4* dK = (float4*)&Ks[r][sg];
            float4* dV = (float4*)&Vs[r][sg];
            if (kj >= 0) {
                const float* kp = g_qkv + (size_t)kj * QKVC + HID + h * DH + sg;
                const float* vp = kp + HID;
                #pragma unroll
                for (int i = 0; i < 4; i++) dK[i] = ((const float4*)kp)[i];
                #pragma unroll
                for (int i = 0; i < 4; i++) dV[i] = ((const float4*)vp)[i];
            } else {
                const float4 z = make_float4(0.f, 0.f, 0.f, 0.f);
                #pragma unroll
                for (int i = 0; i < 4; i++) { dK[i] = z; dV[i] = z; }
            }
        }
        __syncthreads();
        int jlo = qw0 - 255 - kbase; if (jlo < 0) jlo = 0;   // warp-uniform
        int jhi = qw0 + 15  - kbase; if (jhi > 63) jhi = 63;
        for (int j = jlo; j <= jhi; j++) {
            float sh_ = 0.f;
            #pragma unroll
            for (int d4 = 0; d4 < 8; d4++) {
                const float4 kv = *(const float4*)&Ks[j][dof + d4 * 4];
                sh_ += q[d4*4+0]*kv.x + q[d4*4+1]*kv.y + q[d4*4+2]*kv.z + q[d4*4+3]*kv.w;
            }
            float s = sh_ + __shfl_xor_sync(0xffffffffu, sh_, 1);
            const int kj  = kbase + j;
            const int dlt = qi - kj;
            const bool valid = (kj >= 0) & (dlt >= 0) & (dlt < WWIN) &
                               (((unsigned)kj & lm) == qseg);
            s = valid ? s * 0.125f : -3e30f;   // invalid -> p underflows to 0
            if (s > m) {
                const float sf = __expf(m - s);
                l *= sf;
                #pragma unroll
                for (int d = 0; d < 32; d++) acc[d] *= sf;
                m = s;
            }
            const float p = __expf(s - m);
            l += p;
            #pragma unroll
            for (int d4 = 0; d4 < 8; d4++) {
                const float4 vv = *(const float4*)&Vs[j][dof + d4 * 4];
                acc[d4*4+0] = fmaf(p, vv.x, acc[d4*4+0]);
                acc[d4*4+1] = fmaf(p, vv.y, acc[d4*4+1]);
                acc[d4*4+2] = fmaf(p, vv.z, acc[d4*4+2]);
                acc[d4*4+3] = fmaf(p, vv.w, acc[d4*4+3]);
            }
        }
    }
    const float inv = 1.f / l;
    __half* op = g_am2 + (size_t)qi * K2 + h * DH + dof;
    #pragma unroll
    for (int g = 0; g < 4; g++) {
        __align__(16) __half tbuf[8];
        #pragma unroll
        for (int j = 0; j < 8; j++)
            tbuf[j] = __float2half_rn(acc[g * 8 + j] * inv);
        *(uint4*)(op + 8 * g) = *(const uint4*)tbuf;
    }
}

// ---------------- launch ----------------
extern "C" void kernel_launch(void* const* d_in, const int* in_sizes, int n_in,
                              void* d_out, int out_size) {
    const float* x        = (const float*)d_in[0];
    const float* psin     = (const float*)d_in[2];
    const float* pcos     = (const float*)d_in[3];
    const float* ln_scale = (const float*)d_in[4];
    const float* ln_off   = (const float*)d_in[5];
    const float* w_in     = (const float*)d_in[6];
    const float* b_in     = (const float*)d_in[7];
    const float* w_out    = (const float*)d_in[8];
    const float* b_out    = (const float*)d_in[9];
    const int*   plen     = (const int*)d_in[10];
    float* out = (float*)d_out;

    float *p_xn = nullptr, *p_qkv = nullptr;
    __half *p_am1 = nullptr, *p_am2 = nullptr, *p_bm1 = nullptr, *p_bm2 = nullptr;
    cudaGetSymbolAddress((void**)&p_xn,  g_xn);
    cudaGetSymbolAddress((void**)&p_qkv, g_qkv);
    cudaGetSymbolAddress((void**)&p_am1, g_am1);
    cudaGetSymbolAddress((void**)&p_am2, g_am2);
    cudaGetSymbolAddress((void**)&p_bm1, g_bm1);
    cudaGetSymbolAddress((void**)&p_bm2, g_bm2);

    static bool attr_set = false;
    const int gsmem = 3 * 32768;   // 96 KB: 3 stages; reused as 128x132 C stage
    if (!attr_set) {
        cudaFuncSetAttribute(gemm_mma, cudaFuncAttributeMaxDynamicSharedMemorySize, gsmem);
        attr_set = true;
    }

    conv_w_kernel<<<dim3((3*HID+INTER)/32, HID/32), 256>>>(w_in,  p_bm1, HID, 3*HID+INTER);
    conv_w_kernel<<<dim3(HID/32, KC2/32),           256>>>(w_out, p_bm2, KC2, HID);

    ln_kernel<<<NTOK, 256>>>(x, ln_scale, ln_off);

    // GEMM1: [NTOK x 5376]
    gemm_mma<<<dim3((3*HID+INTER)/128, NTOK/128), 256, gsmem>>>(
        p_am1, p_bm1, b_in, nullptr, nullptr, p_qkv, p_am2, K1, 1);

    rope_kernel<<<(NTOK * 768) / 256, 256>>>(psin, pcos);

    attn_kernel<<<dim3(NTOK/128, NHEAD), 256>>>(plen);

    // GEMM2: out = xn + am2 @ bm2^T + b_out
    gemm_mma<<<dim3(HID/128, NTOK/128), 256, gsmem>>>(
        p_am2, p_bm2, b_out, p_xn, out, nullptr, nullptr, K2, 2);
}

// round 11
// speedup vs baseline: 3.1809x; 1.7643x over previous
#include <cuda_runtime.h>
#include <cuda_fp16.h>
#include <math.h>
#include <stdint.h>

#define HID    768
#define INTER  3072
#define NHEAD  12
#define DH     64
#define NTOK   16384
#define WWIN   256
#define K1     HID
#define KC2    (HID + INTER)
#define K2     KC2
#define QKVC   (3 * HID)

__device__ __align__(256) float   g_xn  [(size_t)NTOK * HID];
__device__ __align__(256) float   g_qkv [(size_t)NTOK * QKVC];
__device__ __align__(256) __half  g_am1 [(size_t)NTOK * K1];
__device__ __align__(256) __half  g_am2 [(size_t)NTOK * K2];
__device__ __align__(256) __half  g_bm1 [(size_t)(3*HID+INTER) * K1];
__device__ __align__(256) __half  g_bm2 [(size_t)HID * K2];

__device__ __forceinline__ uint32_t smem_u32(const void* p) {
    uint32_t a;
    asm("{ .reg .u64 t; cvta.to.shared.u64 t, %1; cvt.u32.u64 %0, t; }" : "=r"(a) : "l"(p));
    return a;
}
#define CPASYNC16(sa, gp) \
    asm volatile("cp.async.cg.shared.global [%0], [%1], 16;" :: "r"(sa), "l"(gp))
#define CP_COMMIT() asm volatile("cp.async.commit_group;" ::: "memory")
#define CP_WAIT1()  asm volatile("cp.async.wait_group 1;" ::: "memory")
#define CP_WAIT0()  asm volatile("cp.async.wait_group 0;" ::: "memory")
#define LDSM4(r0, r1, r2, r3, ad) \
    asm volatile("ldmatrix.sync.aligned.m8n8.x4.shared.b16 {%0,%1,%2,%3}, [%4];" \
                 : "=r"(r0), "=r"(r1), "=r"(r2), "=r"(r3) : "r"(ad))
#define MMA16816(d, a, b0, b1) \
    asm volatile("mma.sync.aligned.m16n8k16.row.col.f32.f16.f16.f32 " \
                 "{%0,%1,%2,%3}, {%4,%5,%6,%7}, {%8,%9}, {%0,%1,%2,%3};" \
                 : "+f"((d)[0]), "+f"((d)[1]), "+f"((d)[2]), "+f"((d)[3]) \
                 : "r"((a)[0]), "r"((a)[1]), "r"((a)[2]), "r"((a)[3]), "r"(b0), "r"(b1))

__device__ __forceinline__ uint32_t h2pack(float x, float y) {
    __half2 t = __floats2half2_rn(x, y);
    return *(uint32_t*)&t;
}

// ---------------- LayerNorm + fp16 A emit ----------------
__global__ void ln_kernel(const float* __restrict__ x,
                          const float* __restrict__ gamma,
                          const float* __restrict__ beta) {
    const int row = blockIdx.x, t = threadIdx.x;
    const float* xr = x + (size_t)row * HID;
    float v0 = xr[t], v1 = xr[t + 256], v2 = xr[t + 512];
    float s  = v0 + v1 + v2;
    float ss = v0 * v0 + v1 * v1 + v2 * v2;
    #pragma unroll
    for (int o = 16; o; o >>= 1) {
        s  += __shfl_xor_sync(0xffffffffu, s,  o);
        ss += __shfl_xor_sync(0xffffffffu, ss, o);
    }
    __shared__ float sh[18];
    if ((t & 31) == 0) { sh[t >> 5] = s; sh[(t >> 5) + 8] = ss; }
    __syncthreads();
    if (t == 0) {
        float S = 0.f, SS = 0.f;
        #pragma unroll
        for (int i = 0; i < 8; i++) { S += sh[i]; SS += sh[i + 8]; }
        float mu  = S * (1.0f / HID);
        float var = SS * (1.0f / HID) - mu * mu;
        sh[16] = mu;
        sh[17] = rsqrtf(var + 1e-5f);
    }
    __syncthreads();
    const float mu = sh[16], rs = sh[17];
    float* o = g_xn + (size_t)row * HID;
    __half* a1 = g_am1 + (size_t)row * K1;
    #pragma unroll
    for (int g = 0; g < 3; g++) {
        const int c = t + g * 256;
        const float v = (g == 0 ? v0 : (g == 1 ? v1 : v2));
        const float y = (v - mu) * rs * gamma[c] + beta[c];
        o[c] = y;
        a1[c] = __float2half_rn(y);
    }
}

// ---------------- weight transpose to fp16 ----------------
__global__ void conv_w_kernel(const float* __restrict__ w, __half* __restrict__ bm,
                              int Kdim, int Ndim) {
    __shared__ float tile[32][33];
    const int k0 = blockIdx.y << 5, n0 = blockIdx.x << 5;
    const int tx = threadIdx.x & 31, tr = threadIdx.x >> 5;
    #pragma unroll
    for (int r = 0; r < 32; r += 8)
        tile[tr + r][tx] = w[(size_t)(k0 + tr + r) * Ndim + n0 + tx];
    __syncthreads();
    const int nl = threadIdx.x & 31;
    const int kq = threadIdx.x >> 5;
    __align__(8) __half t[4];
    #pragma unroll
    for (int j = 0; j < 4; j++)
        t[j] = __float2half_rn(tile[kq * 4 + j][nl]);
    uint2* dp = (uint2*)(bm + (size_t)(n0 + nl) * (size_t)Kdim + (size_t)(k0 + kq * 4));
    *dp = *(const uint2*)t;
}

// ---------------- GEMM (as round 10) + fused RoPE in mode-1 epilogue ----------------
__global__ __launch_bounds__(256)
void gemm_mma(const __half* __restrict__ A, const __half* __restrict__ B,
              const float* __restrict__ bias, const float* __restrict__ resid,
              float* __restrict__ outF, float* __restrict__ outQKV,
              __half* __restrict__ outT,
              const float* __restrict__ psin, const float* __restrict__ pcos,
              int K, int mode)
{
    extern __shared__ char sm[];
    const uint32_t sb = smem_u32(sm);
    const int tid = threadIdx.x, lane = tid & 31, wid = tid >> 5;
    const int m0 = blockIdx.y << 7, n0 = blockIdx.x << 7;
    const int wm = wid & 3, wn = wid >> 2;

    auto load_stage = [&](int c, int s) {
        const int kc = c << 6;
        const __half* Ab = A + (size_t)m0 * K + kc;
        const __half* Bb = B + (size_t)n0 * K + kc;
        const uint32_t stA = sb + s * 32768;
        const uint32_t stB = stA + 16384;
        #pragma unroll
        for (int i = 0; i < 4; i++) {
            const int cid = tid + (i << 8);
            const int row = cid >> 3, ch = cid & 7;
            const uint32_t so = row * 128 + ((ch ^ (row & 7)) << 4);
            CPASYNC16(stA + so, Ab + (size_t)row * K + (ch << 3));
            CPASYNC16(stB + so, Bb + (size_t)row * K + (ch << 3));
        }
    };

    const int la = lane & 7;
    const int rowA0 = wm * 32 + la + ((lane >> 3) & 1) * 8;
    const int swA   = rowA0 & 7;
    const int cbA   = (lane >> 4) & 1;
    const int rowB0 = wn * 64 + la + ((lane >> 4) & 1) * 8;
    const int swB   = rowB0 & 7;
    const int cbB   = (lane >> 3) & 1;

    float acc[2][8][4];
    #pragma unroll
    for (int i = 0; i < 2; i++)
        #pragma unroll
        for (int j = 0; j < 8; j++)
            #pragma unroll
            for (int q = 0; q < 4; q++) acc[i][j][q] = 0.f;

    const int nc = K >> 6;
    load_stage(0, 0); CP_COMMIT();
    load_stage(1, 1); CP_COMMIT();

    for (int c = 0; c < nc; c++) {
        CP_WAIT1();
        __syncthreads();
        if (c + 2 < nc) load_stage(c + 2, (c + 2) % 3);
        CP_COMMIT();

        const uint32_t stA = sb + (c % 3) * 32768;
        const uint32_t stB = stA + 16384;
        #pragma unroll
        for (int kk = 0; kk < 4; kk++) {
            uint32_t a[2][4];
            #pragma unroll
            for (int mf = 0; mf < 2; mf++) {
                const uint32_t ad = stA + (rowA0 + mf * 16) * 128 + (((kk * 2 + cbA) ^ swA) << 4);
                LDSM4(a[mf][0], a[mf][1], a[mf][2], a[mf][3], ad);
            }
            uint32_t b[4][4];
            #pragma unroll
            for (int nf2 = 0; nf2 < 4; nf2++) {
                const uint32_t bd = stB + (rowB0 + nf2 * 16) * 128 + (((kk * 2 + cbB) ^ swB) << 4);
                LDSM4(b[nf2][0], b[nf2][1], b[nf2][2], b[nf2][3], bd);
            }
            #pragma unroll
            for (int mf = 0; mf < 2; mf++)
                #pragma unroll
                for (int nf = 0; nf < 8; nf++)
                    MMA16816(acc[mf][nf], a[mf], b[nf >> 1][(nf & 1) * 2], b[nf >> 1][(nf & 1) * 2 + 1]);
        }
        __syncthreads();
    }
    CP_WAIT0();
    __syncthreads();

    float* smC = (float*)sm;
    #pragma unroll
    for (int mf = 0; mf < 2; mf++)
        #pragma unroll
        for (int nf = 0; nf < 8; nf++)
            #pragma unroll
            for (int q = 0; q < 4; q++) {
                const int row = wm * 32 + mf * 16 + (lane >> 2) + ((q >> 1) << 3);
                const int col = wn * 64 + nf * 8 + ((lane & 3) << 1) + (q & 1);
                smC[row * 132 + col] = acc[mf][nf][q];
            }
    __syncthreads();

    const int r  = tid >> 1, hf = tid & 1;
    const int mrow = m0 + r;
    const int nb   = n0 + hf * 64;
    const float* cr = smC + r * 132 + hf * 64;

    if (mode == 1) {
        if (nb < 3 * HID) {
            float vb[64];
            #pragma unroll
            for (int i = 0; i < 64; i++) vb[i] = cr[i] + bias[nb + i];
            if (nb < 2 * HID) {   // fused RoPE (64-col span == one head)
                const float* sp  = psin + (size_t)mrow * DH;
                const float* cp2 = pcos + (size_t)mrow * DH;
                #pragma unroll
                for (int i = 0; i < 32; i++) {
                    const float e = vb[2*i], o = vb[2*i+1];
                    const float sn = sp[2*i], cs = cp2[2*i];
                    vb[2*i]   = e * cs - o * sn;
                    vb[2*i+1] = o * cs + e * sn;
                }
            }
            float* dst = outQKV + (size_t)mrow * QKVC + nb;
            #pragma unroll
            for (int q = 0; q < 16; q++)
                *(float4*)(dst + q*4) = make_float4(vb[q*4], vb[q*4+1], vb[q*4+2], vb[q*4+3]);
        } else {
            __align__(16) __half pr[64];
            #pragma unroll
            for (int i = 0; i < 64; i++) {
                float v = cr[i] + bias[nb + i];
                float u = v * (0.7978845608028654f + 0.0356774081f * v * v);
                v = 0.5f * v * (1.0f + tanhf(u));
                pr[i] = __float2half_rn(v);
            }
            uint4* dp = (uint4*)(outT + (size_t)mrow * K2 + (nb - 2 * HID));
            const uint4* ts = (const uint4*)pr;
            #pragma unroll
            for (int j = 0; j < 8; j++) dp[j] = ts[j];
        }
    } else {
        float* dst = outF + (size_t)mrow * HID + nb;
        const float* rp = resid + (size_t)mrow * HID + nb;
        #pragma unroll
        for (int q = 0; q < 16; q++) {
            float4 rv = *(const float4*)(rp + q * 4);
            float4 ov;
            ov.x = cr[q*4+0] + bias[nb+q*4+0] + rv.x;
            ov.y = cr[q*4+1] + bias[nb+q*4+1] + rv.y;
            ov.z = cr[q*4+2] + bias[nb+q*4+2] + rv.z;
            ov.w = cr[q*4+3] + bias[nb+q*4+3] + rv.w;
            *(float4*)(dst + q * 4) = ov;
        }
    }
}

// ---------------- flash attention with mma.sync ----------------
__global__ __launch_bounds__(256, 2)
void attn_mma(const int* __restrict__ plen) {
    __shared__ __align__(16) __half Qs[128 * 64];
    __shared__ __align__(16) __half Ks[64 * 64];
    __shared__ __align__(16) __half Vt[64 * 72];
    const int h  = blockIdx.y;
    const int q0 = blockIdx.x << 7;
    const int tid = threadIdx.x, lane = tid & 31, wid = tid >> 5;
    const unsigned lm = ~((unsigned)(*plen) - 1u);

    {   // load Q tile (x 1/8) into swizzled smem
        const int r = tid >> 1, d0 = (tid & 1) << 5;
        const float* qp = g_qkv + (size_t)(q0 + r) * QKVC + h * DH + d0;
        #pragma unroll
        for (int i = 0; i < 8; i++) {
            float4 v = *(const float4*)(qp + i * 4);
            const int d = d0 + i * 4;
            const uint32_t so = r * 128 + (((d >> 3) ^ (r & 7)) << 4) + (d & 7) * 2;
            *(__half2*)((char*)Qs + so)     = __floats2half2_rn(v.x * 0.125f, v.y * 0.125f);
            *(__half2*)((char*)Qs + so + 4) = __floats2half2_rn(v.z * 0.125f, v.w * 0.125f);
        }
    }
    __syncthreads();

    uint32_t qf[4][4];
    {
        const uint32_t sq = smem_u32(Qs);
        const int rowq = wid * 16 + (lane & 7) + ((lane >> 3) & 1) * 8;
        const int sw = rowq & 7, cb = (lane >> 4) & 1;
        #pragma unroll
        for (int kk = 0; kk < 4; kk++) {
            const uint32_t ad = sq + rowq * 128 + (((kk * 2 + cb) ^ sw) << 4);
            LDSM4(qf[kk][0], qf[kk][1], qf[kk][2], qf[kk][3], ad);
        }
    }

    float m0 = -1e30f, m1 = -1e30f, l0 = 0.f, l1 = 0.f;
    float acc[8][4];
    #pragma unroll
    for (int i = 0; i < 8; i++) { acc[i][0] = acc[i][1] = acc[i][2] = acc[i][3] = 0.f; }

    const int gr = lane >> 2, gc = (lane & 3) << 1;
    const int qr0 = q0 + wid * 16 + gr;
    const unsigned sega = (unsigned)qr0 & lm;
    const unsigned segb = (unsigned)(qr0 + 8) & lm;

    const uint32_t sk = smem_u32(Ks);
    const uint32_t sv = smem_u32(Vt);
    const int rowk = (lane & 7) + ((lane >> 4) & 1) * 8;
    const int swk  = rowk & 7;
    const int cbk  = (lane >> 3) & 1;
    const int wq0  = q0 + wid * 16;

    for (int t = 0; t < 6; t++) {
        const int kbase = q0 - 256 + t * 64;
        __syncthreads();
        {   // K (swizzled) + V transposed
            const int r = tid >> 2, d0 = (tid & 3) << 4;
            const int kj = kbase + r;
            const float* kp = g_qkv + (size_t)kj * QKVC + HID + h * DH + d0;
            #pragma unroll
            for (int i = 0; i < 4; i++) {
                const int d = d0 + i * 4;
                const uint32_t so = r * 128 + (((d >> 3) ^ (r & 7)) << 4) + (d & 7) * 2;
                if (kj >= 0) {
                    float4 kv = *(const float4*)(kp + i * 4);
                    float4 vv = *(const float4*)(kp + HID + i * 4);
                    *(__half2*)((char*)Ks + so)     = __floats2half2_rn(kv.x, kv.y);
                    *(__half2*)((char*)Ks + so + 4) = __floats2half2_rn(kv.z, kv.w);
                    Vt[(d+0)*72 + r] = __float2half_rn(vv.x);
                    Vt[(d+1)*72 + r] = __float2half_rn(vv.y);
                    Vt[(d+2)*72 + r] = __float2half_rn(vv.z);
                    Vt[(d+3)*72 + r] = __float2half_rn(vv.w);
                } else {
                    const __half2 z = __float2half2_rn(0.f);
                    *(__half2*)((char*)Ks + so)     = z;
                    *(__half2*)((char*)Ks + so + 4) = z;
                    const __half hz = __float2half_rn(0.f);
                    Vt[(d+0)*72 + r] = hz; Vt[(d+1)*72 + r] = hz;
                    Vt[(d+2)*72 + r] = hz; Vt[(d+3)*72 + r] = hz;
                }
            }
        }
        __syncthreads();

        const bool active = (wq0 + 15 >= kbase) && (wq0 - kbase - 63 <= (WWIN - 1));
        if (active) {
            float s[8][4];
            #pragma unroll
            for (int i = 0; i < 8; i++) { s[i][0] = s[i][1] = s[i][2] = s[i][3] = 0.f; }
            #pragma unroll
            for (int kk = 0; kk < 4; kk++) {
                uint32_t b[4][4];
                #pragma unroll
                for (int n2 = 0; n2 < 4; n2++) {
                    const uint32_t ad = sk + (rowk + n2 * 16) * 128 + (((kk * 2 + cbk) ^ swk) << 4);
                    LDSM4(b[n2][0], b[n2][1], b[n2][2], b[n2][3], ad);
                }
                #pragma unroll
                for (int nf = 0; nf < 8; nf++)
                    MMA16816(s[nf], qf[kk], b[nf >> 1][(nf & 1) * 2], b[nf >> 1][(nf & 1) * 2 + 1]);
            }
            float ra = -3e30f, rb = -3e30f;
            #pragma unroll
            for (int nf = 0; nf < 8; nf++) {
                const int ka = kbase + nf * 8 + gc;
                const int kb = ka + 1;
                const bool va0 = (ka >= 0) & (qr0 >= ka) & (qr0 - ka < WWIN) & (((unsigned)ka & lm) == sega);
                const bool va1 = (kb >= 0) & (qr0 >= kb) & (qr0 - kb < WWIN) & (((unsigned)kb & lm) == sega);
                const bool vb0 = (ka >= 0) & (qr0 + 8 >= ka) & (qr0 + 8 - ka < WWIN) & (((unsigned)ka & lm) == segb);
                const bool vb1 = (kb >= 0) & (qr0 + 8 >= kb) & (qr0 + 8 - kb < WWIN) & (((unsigned)kb & lm) == segb);
                s[nf][0] = va0 ? s[nf][0] : -3e30f;
                s[nf][1] = va1 ? s[nf][1] : -3e30f;
                s[nf][2] = vb0 ? s[nf][2] : -3e30f;
                s[nf][3] = vb1 ? s[nf][3] : -3e30f;
                ra = fmaxf(ra, fmaxf(s[nf][0], s[nf][1]));
                rb = fmaxf(rb, fmaxf(s[nf][2], s[nf][3]));
            }
            ra = fmaxf(ra, __shfl_xor_sync(0xffffffffu, ra, 1));
            ra = fmaxf(ra, __shfl_xor_sync(0xffffffffu, ra, 2));
            rb = fmaxf(rb, __shfl_xor_sync(0xffffffffu, rb, 1));
            rb = fmaxf(rb, __shfl_xor_sync(0xffffffffu, rb, 2));
            const float mn0 = fmaxf(m0, ra), mn1 = fmaxf(m1, rb);
            const float sf0 = __expf(m0 - mn0), sf1 = __expf(m1 - mn1);
            m0 = mn0; m1 = mn1;
            l0 *= sf0; l1 *= sf1;
            #pragma unroll
            for (int nf = 0; nf < 8; nf++) {
                acc[nf][0] *= sf0; acc[nf][1] *= sf0;
                acc[nf][2] *= sf1; acc[nf][3] *= sf1;
            }
            float rs0 = 0.f, rs1 = 0.f;
            #pragma unroll
            for (int nf = 0; nf < 8; nf++) {
                s[nf][0] = __expf(s[nf][0] - m0);
                s[nf][1] = __expf(s[nf][1] - m0);
                s[nf][2] = __expf(s[nf][2] - m1);
                s[nf][3] = __expf(s[nf][3] - m1);
                rs0 += s[nf][0] + s[nf][1];
                rs1 += s[nf][2] + s[nf][3];
            }
            rs0 += __shfl_xor_sync(0xffffffffu, rs0, 1);
            rs0 += __shfl_xor_sync(0xffffffffu, rs0, 2);
            rs1 += __shfl_xor_sync(0xffffffffu, rs1, 1);
            rs1 += __shfl_xor_sync(0xffffffffu, rs1, 2);
            l0 += rs0; l1 += rs1;

            #pragma unroll
            for (int kt = 0; kt < 4; kt++) {
                uint32_t a[4];
                a[0] = h2pack(s[2*kt][0],   s[2*kt][1]);
                a[1] = h2pack(s[2*kt][2],   s[2*kt][3]);
                a[2] = h2pack(s[2*kt+1][0], s[2*kt+1][1]);
                a[3] = h2pack(s[2*kt+1][2], s[2*kt+1][3]);
                #pragma unroll
                for (int n2 = 0; n2 < 4; n2++) {
                    uint32_t b[4];
                    const uint32_t ad = sv + (uint32_t)(n2 * 16 + rowk) * 144 + (kt * 16 + cbk * 8) * 2;
                    LDSM4(b[0], b[1], b[2], b[3], ad);
                    MMA16816(acc[n2 * 2],     a, b[0], b[1]);
                    MMA16816(acc[n2 * 2 + 1], a, b[2], b[3]);
                }
            }
        }
    }

    const float i0 = 1.f / l0, i1 = 1.f / l1;
    __half* op0 = g_am2 + (size_t)qr0 * K2 + h * DH + gc;
    __half* op1 = op0 + (size_t)8 * K2;
    #pragma unroll
    for (int nf = 0; nf < 8; nf++) {
        uint32_t w0 = h2pack(acc[nf][0] * i0, acc[nf][1] * i0);
        uint32_t w1 = h2pack(acc[nf][2] * i1, acc[nf][3] * i1);
        *(uint32_t*)(op0 + nf * 8) = w0;
        *(uint32_t*)(op1 + nf * 8) = w1;
    }
}

// ---------------- launch ----------------
extern "C" void kernel_launch(void* const* d_in, const int* in_sizes, int n_in,
                              void* d_out, int out_size) {
    const float* x        = (const float*)d_in[0];
    const float* psin     = (const float*)d_in[2];
    const float* pcos     = (const float*)d_in[3];
    const float* ln_scale = (const float*)d_in[4];
    const float* ln_off   = (const float*)d_in[5];
    const float* w_in     = (const float*)d_in[6];
    const float* b_in     = (const float*)d_in[7];
    const float* w_out    = (const float*)d_in[8];
    const float* b_out    = (const float*)d_in[9];
    const int*   plen     = (const int*)d_in[10];
    float* out = (float*)d_out;

    float *p_xn = nullptr, *p_qkv = nullptr;
    __half *p_am1 = nullptr, *p_am2 = nullptr, *p_bm1 = nullptr, *p_bm2 = nullptr;
    cudaGetSymbolAddress((void**)&p_xn,  g_xn);
    cudaGetSymbolAddress((void**)&p_qkv, g_qkv);
    cudaGetSymbolAddress((void**)&p_am1, g_am1);
    cudaGetSymbolAddress((void**)&p_am2, g_am2);
    cudaGetSymbolAddress((void**)&p_bm1, g_bm1);
    cudaGetSymbolAddress((void**)&p_bm2, g_bm2);

    static bool attr_set = false;
    const int gsmem = 3 * 32768;
    if (!attr_set) {
        cudaFuncSetAttribute(gemm_mma, cudaFuncAttributeMaxDynamicSharedMemorySize, gsmem);
        attr_set = true;
    }

    conv_w_kernel<<<dim3((3*HID+INTER)/32, HID/32), 256>>>(w_in,  p_bm1, HID, 3*HID+INTER);
    conv_w_kernel<<<dim3(HID/32, KC2/32),           256>>>(w_out, p_bm2, KC2, HID);

    ln_kernel<<<NTOK, 256>>>(x, ln_scale, ln_off);

    gemm_mma<<<dim3((3*HID+INTER)/128, NTOK/128), 256, gsmem>>>(
        p_am1, p_bm1, b_in, nullptr, nullptr, p_qkv, p_am2, psin, pcos, K1, 1);

    attn_mma<<<dim3(NTOK/128, NHEAD), 256>>>(plen);

    gemm_mma<<<dim3(HID/128, NTOK/128), 256, gsmem>>>(
        p_am2, p_bm2, b_out, p_xn, out, nullptr, nullptr, nullptr, nullptr, K2, 2);
}

// round 12
// speedup vs baseline: 3.4628x; 1.0886x over previous
#include <cuda_runtime.h>
#include <cuda_fp16.h>
#include <math.h>
#include <stdint.h>

#define HID    768
#define INTER  3072
#define NHEAD  12
#define DH     64
#define NTOK   16384
#define WWIN   256
#define K1     HID
#define KC2    (HID + INTER)
#define K2     KC2
#define QKVC   (3 * HID)     // 2304 fp16 qkv cols

__device__ __align__(256) float   g_xn   [(size_t)NTOK * HID];
__device__ __align__(256) __half  g_qkvh [(size_t)NTOK * QKVC];   // q(prescaled)|k|v fp16
__device__ __align__(256) __half  g_am1  [(size_t)NTOK * K1];
__device__ __align__(256) __half  g_am2  [(size_t)NTOK * K2];
__device__ __align__(256) __half  g_bm1  [(size_t)(3*HID+INTER) * K1];
__device__ __align__(256) __half  g_bm2  [(size_t)HID * K2];

__device__ __forceinline__ uint32_t smem_u32(const void* p) {
    uint32_t a;
    asm("{ .reg .u64 t; cvta.to.shared.u64 t, %1; cvt.u32.u64 %0, t; }" : "=r"(a) : "l"(p));
    return a;
}
#define CPASYNC16(sa, gp) \
    asm volatile("cp.async.cg.shared.global [%0], [%1], 16;" :: "r"(sa), "l"(gp))
#define CPASYNC16Z(sa, gp) \
    asm volatile("cp.async.cg.shared.global [%0], [%1], 16, 0;" :: "r"(sa), "l"(gp))
#define CP_COMMIT() asm volatile("cp.async.commit_group;" ::: "memory")
#define CP_WAIT1()  asm volatile("cp.async.wait_group 1;" ::: "memory")
#define CP_WAIT0()  asm volatile("cp.async.wait_group 0;" ::: "memory")
#define LDSM4(r0, r1, r2, r3, ad) \
    asm volatile("ldmatrix.sync.aligned.m8n8.x4.shared.b16 {%0,%1,%2,%3}, [%4];" \
                 : "=r"(r0), "=r"(r1), "=r"(r2), "=r"(r3) : "r"(ad))
#define LDSM4T(r0, r1, r2, r3, ad) \
    asm volatile("ldmatrix.sync.aligned.m8n8.x4.trans.shared.b16 {%0,%1,%2,%3}, [%4];" \
                 : "=r"(r0), "=r"(r1), "=r"(r2), "=r"(r3) : "r"(ad))
#define MMA16816(d, a, b0, b1) \
    asm volatile("mma.sync.aligned.m16n8k16.row.col.f32.f16.f16.f32 " \
                 "{%0,%1,%2,%3}, {%4,%5,%6,%7}, {%8,%9}, {%0,%1,%2,%3};" \
                 : "+f"((d)[0]), "+f"((d)[1]), "+f"((d)[2]), "+f"((d)[3]) \
                 : "r"((a)[0]), "r"((a)[1]), "r"((a)[2]), "r"((a)[3]), "r"(b0), "r"(b1))

__device__ __forceinline__ uint32_t h2pack(float x, float y) {
    __half2 t = __floats2half2_rn(x, y);
    return *(uint32_t*)&t;
}

// ---------------- LayerNorm + fp16 A emit ----------------
__global__ void ln_kernel(const float* __restrict__ x,
                          const float* __restrict__ gamma,
                          const float* __restrict__ beta) {
    const int row = blockIdx.x, t = threadIdx.x;
    const float* xr = x + (size_t)row * HID;
    float v0 = xr[t], v1 = xr[t + 256], v2 = xr[t + 512];
    float s  = v0 + v1 + v2;
    float ss = v0 * v0 + v1 * v1 + v2 * v2;
    #pragma unroll
    for (int o = 16; o; o >>= 1) {
        s  += __shfl_xor_sync(0xffffffffu, s,  o);
        ss += __shfl_xor_sync(0xffffffffu, ss, o);
    }
    __shared__ float sh[18];
    if ((t & 31) == 0) { sh[t >> 5] = s; sh[(t >> 5) + 8] = ss; }
    __syncthreads();
    if (t == 0) {
        float S = 0.f, SS = 0.f;
        #pragma unroll
        for (int i = 0; i < 8; i++) { S += sh[i]; SS += sh[i + 8]; }
        float mu  = S * (1.0f / HID);
        float var = SS * (1.0f / HID) - mu * mu;
        sh[16] = mu;
        sh[17] = rsqrtf(var + 1e-5f);
    }
    __syncthreads();
    const float mu = sh[16], rs = sh[17];
    float* o = g_xn + (size_t)row * HID;
    __half* a1 = g_am1 + (size_t)row * K1;
    #pragma unroll
    for (int g = 0; g < 3; g++) {
        const int c = t + g * 256;
        const float v = (g == 0 ? v0 : (g == 1 ? v1 : v2));
        const float y = (v - mu) * rs * gamma[c] + beta[c];
        o[c] = y;
        a1[c] = __float2half_rn(y);
    }
}

// ---------------- weight transpose to fp16 ----------------
__global__ void conv_w_kernel(const float* __restrict__ w, __half* __restrict__ bm,
                              int Kdim, int Ndim) {
    __shared__ float tile[32][33];
    const int k0 = blockIdx.y << 5, n0 = blockIdx.x << 5;
    const int tx = threadIdx.x & 31, tr = threadIdx.x >> 5;
    #pragma unroll
    for (int r = 0; r < 32; r += 8)
        tile[tr + r][tx] = w[(size_t)(k0 + tr + r) * Ndim + n0 + tx];
    __syncthreads();
    const int nl = threadIdx.x & 31;
    const int kq = threadIdx.x >> 5;
    __align__(8) __half t[4];
    #pragma unroll
    for (int j = 0; j < 4; j++)
        t[j] = __float2half_rn(tile[kq * 4 + j][nl]);
    uint2* dp = (uint2*)(bm + (size_t)(n0 + nl) * (size_t)Kdim + (size_t)(k0 + kq * 4));
    *dp = *(const uint2*)t;
}

// ---------------- GEMM: C[M,N] = A[M,K] * B[N,K]^T ----------------
// mode 1: qkv -> fp16 outH (RoPE on q,k; q pre-scaled 1/8) + gelu fp16 -> outT
// mode 2: outF = acc + bias + resid
__global__ __launch_bounds__(256)
void gemm_mma(const __half* __restrict__ A, const __half* __restrict__ B,
              const float* __restrict__ bias, const float* __restrict__ resid,
              float* __restrict__ outF, __half* __restrict__ outH,
              __half* __restrict__ outT,
              const float* __restrict__ psin, const float* __restrict__ pcos,
              int K, int mode)
{
    extern __shared__ char sm[];
    const uint32_t sb = smem_u32(sm);
    const int tid = threadIdx.x, lane = tid & 31, wid = tid >> 5;
    const int m0 = blockIdx.y << 7, n0 = blockIdx.x << 7;
    const int wm = wid & 3, wn = wid >> 2;

    auto load_stage = [&](int c, int s) {
        const int kc = c << 6;
        const __half* Ab = A + (size_t)m0 * K + kc;
        const __half* Bb = B + (size_t)n0 * K + kc;
        const uint32_t stA = sb + s * 32768;
        const uint32_t stB = stA + 16384;
        #pragma unroll
        for (int i = 0; i < 4; i++) {
            const int cid = tid + (i << 8);
            const int row = cid >> 3, ch = cid & 7;
            const uint32_t so = row * 128 + ((ch ^ (row & 7)) << 4);
            CPASYNC16(stA + so, Ab + (size_t)row * K + (ch << 3));
            CPASYNC16(stB + so, Bb + (size_t)row * K + (ch << 3));
        }
    };

    const int la = lane & 7;
    const int rowA0 = wm * 32 + la + ((lane >> 3) & 1) * 8;
    const int swA   = rowA0 & 7;
    const int cbA   = (lane >> 4) & 1;
    const int rowB0 = wn * 64 + la + ((lane >> 4) & 1) * 8;
    const int swB   = rowB0 & 7;
    const int cbB   = (lane >> 3) & 1;

    float acc[2][8][4];
    #pragma unroll
    for (int i = 0; i < 2; i++)
        #pragma unroll
        for (int j = 0; j < 8; j++)
            #pragma unroll
            for (int q = 0; q < 4; q++) acc[i][j][q] = 0.f;

    const int nc = K >> 6;
    load_stage(0, 0); CP_COMMIT();
    load_stage(1, 1); CP_COMMIT();

    for (int c = 0; c < nc; c++) {
        CP_WAIT1();
        __syncthreads();
        if (c + 2 < nc) load_stage(c + 2, (c + 2) % 3);
        CP_COMMIT();

        const uint32_t stA = sb + (c % 3) * 32768;
        const uint32_t stB = stA + 16384;
        #pragma unroll
        for (int kk = 0; kk < 4; kk++) {
            uint32_t a[2][4];
            #pragma unroll
            for (int mf = 0; mf < 2; mf++) {
                const uint32_t ad = stA + (rowA0 + mf * 16) * 128 + (((kk * 2 + cbA) ^ swA) << 4);
                LDSM4(a[mf][0], a[mf][1], a[mf][2], a[mf][3], ad);
            }
            uint32_t b[4][4];
            #pragma unroll
            for (int nf2 = 0; nf2 < 4; nf2++) {
                const uint32_t bd = stB + (rowB0 + nf2 * 16) * 128 + (((kk * 2 + cbB) ^ swB) << 4);
                LDSM4(b[nf2][0], b[nf2][1], b[nf2][2], b[nf2][3], bd);
            }
            #pragma unroll
            for (int mf = 0; mf < 2; mf++)
                #pragma unroll
                for (int nf = 0; nf < 8; nf++)
                    MMA16816(acc[mf][nf], a[mf], b[nf >> 1][(nf & 1) * 2], b[nf >> 1][(nf & 1) * 2 + 1]);
        }
        // no trailing sync: the barrier at the top of the next iteration
        // separates this compute from the next overwrite of this stage.
    }
    __syncthreads();

    float* smC = (float*)sm;
    #pragma unroll
    for (int mf = 0; mf < 2; mf++)
        #pragma unroll
        for (int nf = 0; nf < 8; nf++)
            #pragma unroll
            for (int q = 0; q < 4; q++) {
                const int row = wm * 32 + mf * 16 + (lane >> 2) + ((q >> 1) << 3);
                const int col = wn * 64 + nf * 8 + ((lane & 3) << 1) + (q & 1);
                smC[row * 132 + col] = acc[mf][nf][q];
            }
    __syncthreads();

    const int r  = tid >> 1, hf = tid & 1;
    const int mrow = m0 + r;
    const int nb   = n0 + hf * 64;
    const float* cr = smC + r * 132 + hf * 64;

    if (mode == 1) {
        if (nb < 3 * HID) {
            float vb[64];
            #pragma unroll
            for (int i = 0; i < 64; i++) vb[i] = cr[i] + bias[nb + i];
            if (nb < 2 * HID) {   // RoPE on q,k (64-col span == one head)
                const float* sp  = psin + (size_t)mrow * DH;
                const float* cp2 = pcos + (size_t)mrow * DH;
                #pragma unroll
                for (int i = 0; i < 32; i++) {
                    const float e = vb[2*i], o = vb[2*i+1];
                    const float sn = sp[2*i], cs = cp2[2*i];
                    vb[2*i]   = e * cs - o * sn;
                    vb[2*i+1] = o * cs + e * sn;
                }
            }
            const float sc = (nb < HID) ? 0.125f : 1.0f;   // pre-scale q
            __align__(16) __half pr[64];
            #pragma unroll
            for (int i = 0; i < 64; i++) pr[i] = __float2half_rn(vb[i] * sc);
            uint4* dp = (uint4*)(outH + (size_t)mrow * QKVC + nb);
            const uint4* ts = (const uint4*)pr;
            #pragma unroll
            for (int j = 0; j < 8; j++) dp[j] = ts[j];
        } else {
            __align__(16) __half pr[64];
            #pragma unroll
            for (int i = 0; i < 64; i++) {
                float v = cr[i] + bias[nb + i];
                float u = v * (0.7978845608028654f + 0.0356774081f * v * v);
                v = 0.5f * v * (1.0f + tanhf(u));
                pr[i] = __float2half_rn(v);
            }
            uint4* dp = (uint4*)(outT + (size_t)mrow * K2 + (nb - 2 * HID));
            const uint4* ts = (const uint4*)pr;
            #pragma unroll
            for (int j = 0; j < 8; j++) dp[j] = ts[j];
        }
    } else {
        float* dst = outF + (size_t)mrow * HID + nb;
        const float* rp = resid + (size_t)mrow * HID + nb;
        #pragma unroll
        for (int q = 0; q < 16; q++) {
            float4 rv = *(const float4*)(rp + q * 4);
            float4 ov;
            ov.x = cr[q*4+0] + bias[nb+q*4+0] + rv.x;
            ov.y = cr[q*4+1] + bias[nb+q*4+1] + rv.y;
            ov.z = cr[q*4+2] + bias[nb+q*4+2] + rv.z;
            ov.w = cr[q*4+3] + bias[nb+q*4+3] + rv.w;
            *(float4*)(dst + q * 4) = ov;
        }
    }
}

// ---------------- flash attention: fp16 feed, cp.async double-buffer, ldmatrix.trans V ----------------
__global__ __launch_bounds__(256, 2)
void attn_mma(const int* __restrict__ plen) {
    __shared__ __align__(16) __half Qs[128 * 64];      // 16 KB
    __shared__ __align__(16) __half Ks[2][64 * 64];    // 16 KB
    __shared__ __align__(16) __half Vs[2][64 * 64];    // 16 KB
    const int h  = blockIdx.y;
    const int q0 = blockIdx.x << 7;
    const int tid = threadIdx.x, lane = tid & 31, wid = tid >> 5;
    const unsigned lm = ~((unsigned)(*plen) - 1u);

    const uint32_t sq  = smem_u32(Qs);
    const uint32_t sk0 = smem_u32(Ks);
    const uint32_t sv0 = smem_u32(Vs);

    // Q tile: 128 rows x 128B, q already pre-scaled by 1/8
    #pragma unroll
    for (int i = 0; i < 4; i++) {
        const int cid = tid + (i << 8);
        const int r = cid >> 3, ch = cid & 7;
        const uint32_t so = r * 128 + ((ch ^ (r & 7)) << 4);
        CPASYNC16(sq + so, g_qkvh + (size_t)(q0 + r) * QKVC + h * DH + (ch << 3));
    }
    CP_COMMIT();

    auto loadkv = [&](int t, int b) {
        const int kbase = q0 - 256 + t * 64;
        const uint32_t skb = sk0 + b * 8192;
        const uint32_t svb = sv0 + b * 8192;
        #pragma unroll
        for (int i = 0; i < 2; i++) {
            const int cid = tid + (i << 8);
            const int r = cid >> 3, ch = cid & 7;
            const int kj = kbase + r;
            const uint32_t so = r * 128 + ((ch ^ (r & 7)) << 4);
            const __half* kp = g_qkvh + (size_t)kj * QKVC + HID + h * DH + (ch << 3);
            if (kj >= 0) {
                CPASYNC16(skb + so, kp);
                CPASYNC16(svb + so, kp + HID);
            } else {
                CPASYNC16Z(skb + so, g_qkvh);
                CPASYNC16Z(svb + so, g_qkvh);
            }
        }
    };
    loadkv(0, 0); CP_COMMIT();

    CP_WAIT1();          // Q group done (tile-0 group may be pending)
    __syncthreads();

    uint32_t qf[4][4];
    {
        const int rowq = wid * 16 + (lane & 7) + ((lane >> 3) & 1) * 8;
        const int sw = rowq & 7, cb = (lane >> 4) & 1;
        #pragma unroll
        for (int kk = 0; kk < 4; kk++) {
            const uint32_t ad = sq + rowq * 128 + (((kk * 2 + cb) ^ sw) << 4);
            LDSM4(qf[kk][0], qf[kk][1], qf[kk][2], qf[kk][3], ad);
        }
    }

    float m0 = -1e30f, m1 = -1e30f, l0 = 0.f, l1 = 0.f;
    float acc[8][4];
    #pragma unroll
    for (int i = 0; i < 8; i++) { acc[i][0] = acc[i][1] = acc[i][2] = acc[i][3] = 0.f; }

    const int gr = lane >> 2, gc = (lane & 3) << 1;
    const int qr0 = q0 + wid * 16 + gr;
    const unsigned sega = (unsigned)qr0 & lm;
    const unsigned segb = (unsigned)(qr0 + 8) & lm;

    const int rowk = (lane & 7) + ((lane >> 4) & 1) * 8;   // QK^T B-frag rows
    const int swk  = rowk & 7;
    const int cbk  = (lane >> 3) & 1;
    const int rvl  = lane & 15;                            // trans-V key row
    const int dvs  = (lane >> 4) << 3;                     // trans-V dim offset
    const int wq0  = q0 + wid * 16;

    for (int t = 0; t < 6; t++) {
        CP_WAIT0();                 // tile t resident (only pending group)
        __syncthreads();
        if (t + 1 < 6) loadkv(t + 1, (t + 1) & 1);
        CP_COMMIT();

        const uint32_t skb = sk0 + (t & 1) * 8192;
        const uint32_t svb = sv0 + (t & 1) * 8192;
        const int kbase = q0 - 256 + t * 64;
        const bool active = (wq0 + 15 >= kbase) && (wq0 - kbase - 63 <= (WWIN - 1));
        if (!active) continue;

        // S = Q @ K^T
        float s[8][4];
        #pragma unroll
        for (int i = 0; i < 8; i++) { s[i][0] = s[i][1] = s[i][2] = s[i][3] = 0.f; }
        #pragma unroll
        for (int kk = 0; kk < 4; kk++) {
            uint32_t b[4][4];
            #pragma unroll
            for (int n2 = 0; n2 < 4; n2++) {
                const uint32_t ad = skb + (rowk + n2 * 16) * 128 + (((kk * 2 + cbk) ^ swk) << 4);
                LDSM4(b[n2][0], b[n2][1], b[n2][2], b[n2][3], ad);
            }
            #pragma unroll
            for (int nf = 0; nf < 8; nf++)
                MMA16816(s[nf], qf[kk], b[nf >> 1][(nf & 1) * 2], b[nf >> 1][(nf & 1) * 2 + 1]);
        }

        // mask + online softmax
        float ra = -3e30f, rb = -3e30f;
        #pragma unroll
        for (int nf = 0; nf < 8; nf++) {
            const int ka = kbase + nf * 8 + gc;
            const int kb = ka + 1;
            const bool va0 = (ka >= 0) & (qr0 >= ka) & (qr0 - ka < WWIN) & (((unsigned)ka & lm) == sega);
            const bool va1 = (kb >= 0) & (qr0 >= kb) & (qr0 - kb < WWIN) & (((unsigned)kb & lm) == sega);
            const bool vb0 = (ka >= 0) & (qr0 + 8 >= ka) & (qr0 + 8 - ka < WWIN) & (((unsigned)ka & lm) == segb);
            const bool vb1 = (kb >= 0) & (qr0 + 8 >= kb) & (qr0 + 8 - kb < WWIN) & (((unsigned)kb & lm) == segb);
            s[nf][0] = va0 ? s[nf][0] : -3e30f;
            s[nf][1] = va1 ? s[nf][1] : -3e30f;
            s[nf][2] = vb0 ? s[nf][2] : -3e30f;
            s[nf][3] = vb1 ? s[nf][3] : -3e30f;
            ra = fmaxf(ra, fmaxf(s[nf][0], s[nf][1]));
            rb = fmaxf(rb, fmaxf(s[nf][2], s[nf][3]));
        }
        ra = fmaxf(ra, __shfl_xor_sync(0xffffffffu, ra, 1));
        ra = fmaxf(ra, __shfl_xor_sync(0xffffffffu, ra, 2));
        rb = fmaxf(rb, __shfl_xor_sync(0xffffffffu, rb, 1));
        rb = fmaxf(rb, __shfl_xor_sync(0xffffffffu, rb, 2));
        const float mn0 = fmaxf(m0, ra), mn1 = fmaxf(m1, rb);
        const float sf0 = __expf(m0 - mn0), sf1 = __expf(m1 - mn1);
        m0 = mn0; m1 = mn1;
        l0 *= sf0; l1 *= sf1;
        #pragma unroll
        for (int nf = 0; nf < 8; nf++) {
            acc[nf][0] *= sf0; acc[nf][1] *= sf0;
            acc[nf][2] *= sf1; acc[nf][3] *= sf1;
        }
        float rs0 = 0.f, rs1 = 0.f;
        #pragma unroll
        for (int nf = 0; nf < 8; nf++) {
            s[nf][0] = __expf(s[nf][0] - m0);
            s[nf][1] = __expf(s[nf][1] - m0);
            s[nf][2] = __expf(s[nf][2] - m1);
            s[nf][3] = __expf(s[nf][3] - m1);
            rs0 += s[nf][0] + s[nf][1];
            rs1 += s[nf][2] + s[nf][3];
        }
        rs0 += __shfl_xor_sync(0xffffffffu, rs0, 1);
        rs0 += __shfl_xor_sync(0xffffffffu, rs0, 2);
        rs1 += __shfl_xor_sync(0xffffffffu, rs1, 1);
        rs1 += __shfl_xor_sync(0xffffffffu, rs1, 2);
        l0 += rs0; l1 += rs1;

        // O += P @ V   (V row-major in smem; B-frags via ldmatrix.trans)
        #pragma unroll
        for (int kt = 0; kt < 4; kt++) {
            uint32_t a[4];
            a[0] = h2pack(s[2*kt][0],   s[2*kt][1]);
            a[1] = h2pack(s[2*kt][2],   s[2*kt][3]);
            a[2] = h2pack(s[2*kt+1][0], s[2*kt+1][1]);
            a[3] = h2pack(s[2*kt+1][2], s[2*kt+1][3]);
            const int rv = kt * 16 + rvl;
            #pragma unroll
            for (int n2 = 0; n2 < 4; n2++) {
                const int dv = n2 * 16 + dvs;
                const uint32_t ad = svb + rv * 128 + ((((dv >> 3)) ^ (rv & 7)) << 4);
                uint32_t b0, b1, b2, b3;
                LDSM4T(b0, b1, b2, b3, ad);
                MMA16816(acc[n2 * 2],     a, b0, b1);
                MMA16816(acc[n2 * 2 + 1], a, b2, b3);
            }
        }
    }

    const float i0 = 1.f / l0, i1 = 1.f / l1;
    __half* op0 = g_am2 + (size_t)qr0 * K2 + h * DH + gc;
    __half* op1 = op0 + (size_t)8 * K2;
    #pragma unroll
    for (int nf = 0; nf < 8; nf++) {
        uint32_t w0 = h2pack(acc[nf][0] * i0, acc[nf][1] * i0);
        uint32_t w1 = h2pack(acc[nf][2] * i1, acc[nf][3] * i1);
        *(uint32_t*)(op0 + nf * 8) = w0;
        *(uint32_t*)(op1 + nf * 8) = w1;
    }
}

// ---------------- launch ----------------
extern "C" void kernel_launch(void* const* d_in, const int* in_sizes, int n_in,
                              void* d_out, int out_size) {
    const float* x        = (const float*)d_in[0];
    const float* psin     = (const float*)d_in[2];
    const float* pcos     = (const float*)d_in[3];
    const float* ln_scale = (const float*)d_in[4];
    const float* ln_off   = (const float*)d_in[5];
    const float* w_in     = (const float*)d_in[6];
    const float* b_in     = (const float*)d_in[7];
    const float* w_out    = (const float*)d_in[8];
    const float* b_out    = (const float*)d_in[9];
    const int*   plen     = (const int*)d_in[10];
    float* out = (float*)d_out;

    float* p_xn = nullptr;
    __half *p_qkvh = nullptr, *p_am1 = nullptr, *p_am2 = nullptr, *p_bm1 = nullptr, *p_bm2 = nullptr;
    cudaGetSymbolAddress((void**)&p_xn,   g_xn);
    cudaGetSymbolAddress((void**)&p_qkvh, g_qkvh);
    cudaGetSymbolAddress((void**)&p_am1,  g_am1);
    cudaGetSymbolAddress((void**)&p_am2,  g_am2);
    cudaGetSymbolAddress((void**)&p_bm1,  g_bm1);
    cudaGetSymbolAddress((void**)&p_bm2,  g_bm2);

    static bool attr_set = false;
    const int gsmem = 3 * 32768;
    if (!attr_set) {
        cudaFuncSetAttribute(gemm_mma, cudaFuncAttributeMaxDynamicSharedMemorySize, gsmem);
        attr_set = true;
    }

    conv_w_kernel<<<dim3((3*HID+INTER)/32, HID/32), 256>>>(w_in,  p_bm1, HID, 3*HID+INTER);
    conv_w_kernel<<<dim3(HID/32, KC2/32),           256>>>(w_out, p_bm2, KC2, HID);

    ln_kernel<<<NTOK, 256>>>(x, ln_scale, ln_off);

    // GEMM1 -> qkv fp16 (RoPE fused, q prescaled) + gelu(ff) fp16
    gemm_mma<<<dim3((3*HID+INTER)/128, NTOK/128), 256, gsmem>>>(
        p_am1, p_bm1, b_in, nullptr, nullptr, p_qkvh, p_am2, psin, pcos, K1, 1);

    attn_mma<<<dim3(NTOK/128, NHEAD), 256>>>(plen);

    // GEMM2: out = xn + [attn|gelu_ff] @ w_out + b_out
    gemm_mma<<<dim3(HID/128, NTOK/128), 256, gsmem>>>(
        p_am2, p_bm2, b_out, p_xn, out, nullptr, nullptr, nullptr, nullptr, K2, 2);
}